// round 13
// baseline (speedup 1.0000x reference)
#include <cuda_runtime.h>
#include <cuda_bf16.h>
#include <math.h>
#include <stdint.h>

typedef __nv_bfloat16 bf16;

#define NN 4096
#define DD 256

// ---------------- scratch (device globals; no allocation) ----------------
__device__ bf16 g_win_h[NN * DD], g_win_l[NN * DD];
__device__ bf16 g_h0_h[NN * DD],  g_h0_l[NN * DD];
__device__ bf16 g_x_h[NN * DD],   g_x_l[NN * DD];
__device__ bf16 g_y_h[NN * DD],   g_y_l[NN * DD];
__device__ bf16 g_t_h[NN * DD],   g_t_l[NN * DD];
__device__ bf16 g_qkv_h[NN * 768], g_qkv_l[NN * 768];
__device__ bf16 g_ff_h[NN * 512],  g_ff_l[NN * 512];
__device__ bf16 g_sim_h[(long)NN * NN], g_sim_l[(long)NN * NN];   // 32MB each
#define WPOOL 1572864
__device__ bf16 g_w_h[WPOOL], g_w_l[WPOOL];
__device__ float g_tb[NN * DD];
__device__ float g_ssrc[NN * 4], g_sdst[NN * 4];
__device__ int   g_idx[NN * 16];

// ---------------- helpers -------------------------------------------------
__device__ __forceinline__ void cp16(uint32_t dst, const void* src) {
    asm volatile("cp.async.cg.shared.global [%0], [%1], 16;" :: "r"(dst), "l"(src));
}
#define CP_COMMIT() asm volatile("cp.async.commit_group;")

__device__ __forceinline__ float rec(const bf16* H, const bf16* L, long i) {
    return __bfloat162float(H[i]) + __bfloat162float(L[i]);
}
__device__ __forceinline__ void split1(float v, bf16* H, bf16* L, long off) {
    bf16 h = __float2bfloat16(v);
    H[off] = h;
    L[off] = __float2bfloat16(v - __bfloat162float(h));
}
__device__ __forceinline__ uint32_t pk(bf16 a, bf16 b) {
    __nv_bfloat162 t = __halves2bfloat162(a, b);
    return *(uint32_t*)&t;
}
__device__ __forceinline__ void split2st(float v0, float v1, bf16* H, bf16* L, long off) {
    bf16 h0 = __float2bfloat16(v0), h1 = __float2bfloat16(v1);
    float r0 = v0 - __bfloat162float(h0), r1 = v1 - __bfloat162float(h1);
    *(uint32_t*)(H + off) = pk(h0, h1);
    *(uint32_t*)(L + off) = pk(__float2bfloat16(r0), __float2bfloat16(r1));
}
__device__ __forceinline__ void splitpk(float v0, float v1, uint32_t& hi, uint32_t& lo) {
    bf16 h0 = __float2bfloat16(v0), h1 = __float2bfloat16(v1);
    hi = pk(h0, h1);
    lo = pk(__float2bfloat16(v0 - __bfloat162float(h0)),
            __float2bfloat16(v1 - __bfloat162float(h1)));
}

#define MMA_BF16(c, a, b0, b1) \
    asm volatile("mma.sync.aligned.m16n8k16.row.col.f32.bf16.bf16.f32 " \
                 "{%0,%1,%2,%3},{%4,%5,%6,%7},{%8,%9},{%0,%1,%2,%3};" \
                 : "+f"((c)[0]), "+f"((c)[1]), "+f"((c)[2]), "+f"((c)[3]) \
                 : "r"((a)[0]), "r"((a)[1]), "r"((a)[2]), "r"((a)[3]), \
                   "r"(b0), "r"(b1))

#define LDSM4(r, addr) \
    asm volatile("ldmatrix.sync.aligned.m8n8.x4.shared.b16 {%0,%1,%2,%3}, [%4];" \
                 : "=r"((r)[0]), "=r"((r)[1]), "=r"((r)[2]), "=r"((r)[3]) \
                 : "r"(addr))

#define LDSM4T(r, addr) \
    asm volatile("ldmatrix.sync.aligned.m8n8.x4.trans.shared.b16 {%0,%1,%2,%3}, [%4];" \
                 : "=r"((r)[0]), "=r"((r)[1]), "=r"((r)[2]), "=r"((r)[3]) \
                 : "r"(addr))

// ---------------- split-bf16 3-product GEMM (both operands k-major) -------
// ACT: 0 none, 1 relu, 2 tanh, 3 accumulate-into-C, 4 qkv (scale cols<256 by 1/8)
template<int BN, int ACT>
__global__ void __launch_bounds__(256) gemm_bf3(
    const bf16* __restrict__ Ah, const bf16* __restrict__ Al, int lda,
    const bf16* __restrict__ Bh, const bf16* __restrict__ Bl, int ldb,
    const float* __restrict__ bias,
    bf16* __restrict__ Ch, bf16* __restrict__ Cl, int ldc,
    int K, long sAz, long sBz, long sCz, float alpha)
{
    constexpr int NI = BN / 32;
    __shared__ bf16 sAh[2][128 * 24], sAl[2][128 * 24];
    __shared__ bf16 sBh[2][BN * 24],  sBl[2][BN * 24];

    const int tid = threadIdx.x;
    const int warp = tid >> 5, lane = tid & 31;
    const int g = lane >> 2, tig = lane & 3;
    const int wm = warp & 1, wn = warp >> 1;
    const int wm0 = wm * 64, wn0 = wn * (BN / 4);
    const int bm = blockIdx.y * 128, bn = blockIdx.x * BN;
    const long z = blockIdx.z;
    Ah += z * sAz; Al += z * sAz;
    Bh += z * sBz; Bl += z * sBz;
    Ch += z * sCz; Cl += z * sCz;

    const uint32_t offA = (uint32_t)(((wm0 + (lane & 15)) * 24 + (lane >> 4) * 8) * 2);
    const uint32_t offB = (uint32_t)(((wn0 + ((lane >> 4) & 1) * 8 + (lane & 7)) * 24
                                      + ((lane >> 3) & 1) * 8) * 2);
    uint32_t bAh[2] = { (uint32_t)__cvta_generic_to_shared(&sAh[0][0]),
                        (uint32_t)__cvta_generic_to_shared(&sAh[1][0]) };
    uint32_t bAl[2] = { (uint32_t)__cvta_generic_to_shared(&sAl[0][0]),
                        (uint32_t)__cvta_generic_to_shared(&sAl[1][0]) };
    uint32_t bBh[2] = { (uint32_t)__cvta_generic_to_shared(&sBh[0][0]),
                        (uint32_t)__cvta_generic_to_shared(&sBh[1][0]) };
    uint32_t bBl[2] = { (uint32_t)__cvta_generic_to_shared(&sBl[0][0]),
                        (uint32_t)__cvta_generic_to_shared(&sBl[1][0]) };

    float acc[4][NI][4];
#pragma unroll
    for (int mi = 0; mi < 4; mi++)
#pragma unroll
        for (int ni = 0; ni < NI; ni++)
#pragma unroll
            for (int q = 0; q < 4; q++) acc[mi][ni][q] = 0.f;

    auto load_tile = [&](int t, int buf) {
        const int k0 = t * 16;
        {
            int row = tid >> 1, half = tid & 1;
            uint32_t off = (uint32_t)(row * 24 + half * 8) * 2;
            long src = (long)(bm + row) * lda + k0 + half * 8;
            cp16(bAh[buf] + off, Ah + src);
            cp16(bAl[buf] + off, Al + src);
        }
        if (BN == 128 || tid < BN * 2) {
            int row = tid >> 1, half = tid & 1;
            uint32_t off = (uint32_t)(row * 24 + half * 8) * 2;
            long src = (long)(bn + row) * ldb + k0 + half * 8;
            cp16(bBh[buf] + off, Bh + src);
            cp16(bBl[buf] + off, Bl + src);
        }
    };

    load_tile(0, 0);
    CP_COMMIT();
    const int nt = K / 16;

    for (int t = 0; t < nt; t++) {
        if (t + 1 < nt) {
            load_tile(t + 1, (t + 1) & 1);
            CP_COMMIT();
            asm volatile("cp.async.wait_group 1;");
        } else {
            asm volatile("cp.async.wait_group 0;");
        }
        __syncthreads();
        const int buf = t & 1;

        uint32_t fah[4][4], fal[4][4];
#pragma unroll
        for (int mi = 0; mi < 4; mi++) {
            LDSM4(fah[mi], bAh[buf] + offA + mi * 768);
            LDSM4(fal[mi], bAl[buf] + offA + mi * 768);
        }
        uint32_t bh[NI][2], bl[NI][2];
#pragma unroll
        for (int pi = 0; pi < NI / 2; pi++) {
            LDSM4(bh[2 * pi], bBh[buf] + offB + pi * 768);
            LDSM4(bl[2 * pi], bBl[buf] + offB + pi * 768);
        }
#pragma unroll
        for (int ni = 0; ni < NI; ni++) {
#pragma unroll
            for (int mi = 0; mi < 4; mi++) {
                MMA_BF16(acc[mi][ni], fah[mi], bh[ni][0], bh[ni][1]);
                MMA_BF16(acc[mi][ni], fal[mi], bh[ni][0], bh[ni][1]);
                MMA_BF16(acc[mi][ni], fah[mi], bl[ni][0], bl[ni][1]);
            }
        }
        __syncthreads();
    }

#pragma unroll
    for (int mi = 0; mi < 4; mi++) {
#pragma unroll
        for (int ni = 0; ni < NI; ni++) {
            int col = bn + wn0 + ni * 8 + tig * 2;
            float b0 = 0.f, b1 = 0.f;
            if (bias) { b0 = bias[col]; b1 = bias[col + 1]; }
#pragma unroll
            for (int h2 = 0; h2 < 2; h2++) {
                int row = bm + wm0 + mi * 16 + g + h2 * 8;
                long off = (long)row * ldc + col;
                float v0 = acc[mi][ni][h2 * 2 + 0] * alpha + b0;
                float v1 = acc[mi][ni][h2 * 2 + 1] * alpha + b1;
                if (ACT == 1) { v0 = fmaxf(v0, 0.f); v1 = fmaxf(v1, 0.f); }
                if (ACT == 2) { v0 = tanhf(v0); v1 = tanhf(v1); }
                if (ACT == 3) { v0 += rec(Ch, Cl, off); v1 += rec(Ch, Cl, off + 1); }
                if (ACT == 4 && col < 256) { v0 *= 0.125f; v1 *= 0.125f; }
                split2st(v0, v1, Ch, Cl, off);
            }
        }
    }
}

// ---------------- fused flash attention (bf3, dual-plane P) ---------------
// grid (32, 4): 128 q-rows per block, head = blockIdx.y. 8 warps * 16 rows.
// Q columns are pre-scaled by 1/8 in the QKV GEMM epilogue (ACT=4).
__global__ void __launch_bounds__(256) flash_attn(
    const bf16* __restrict__ Qh, const bf16* __restrict__ Ql,
    bf16* __restrict__ Oh, bf16* __restrict__ Ol)
{
    __shared__ char smem[2 * 18432];   // Q staging, then KV double buffer
    const int tid = threadIdx.x, lane = tid & 31, w = tid >> 5;
    const int g = lane >> 2, tig = lane & 3;
    const int q0 = blockIdx.x * 128;
    const int h = blockIdx.y;
    const uint32_t sbase = (uint32_t)__cvta_generic_to_shared(smem);

    // ---- stage Q tile (128x64, dual plane, stride 72 elems = 144B)
#pragma unroll
    for (int c = tid; c < 1024; c += 256) {
        int row = c >> 3, off = (c & 7) * 8;
        long src = (long)(q0 + row) * 768 + h * 64 + off;
        cp16(sbase + row * 144 + off * 2, Qh + src);
        cp16(sbase + 18432 + row * 144 + off * 2, Ql + src);
    }
    CP_COMMIT();
    asm volatile("cp.async.wait_group 0;");
    __syncthreads();

    uint32_t fqh[4][4], fql[4][4];
    {
        uint32_t offQ = (uint32_t)(((w * 16 + (lane & 15)) * 72 + (lane >> 4) * 8) * 2);
#pragma unroll
        for (int j = 0; j < 4; j++) {
            LDSM4(fqh[j], sbase + offQ + j * 32);
            LDSM4(fql[j], sbase + 18432 + offQ + j * 32);
        }
    }
    __syncthreads();   // Q reads done; smem reused as K/V buffers

    // KV buffer layout per stage (18432B): kh 0 / kl 4608 / vh 9216 / vl 13824
    auto load_kv = [&](int t, int b) {
        uint32_t base = sbase + b * 18432;
        int row = tid >> 3, off = (tid & 7) * 8;
        long key = (long)t * 32 + row;
        long srcK = key * 768 + 256 + h * 64 + off;
        long srcV = key * 768 + 512 + h * 64 + off;
        uint32_t d = row * 144 + off * 2;
        cp16(base + d,         Qh + srcK);
        cp16(base + 4608 + d,  Ql + srcK);
        cp16(base + 9216 + d,  Qh + srcV);
        cp16(base + 13824 + d, Ql + srcV);
    };

    const uint32_t offK = (uint32_t)(((((lane >> 4) & 1) * 8 + (lane & 7)) * 72
                                      + ((lane >> 3) & 1) * 8) * 2);
    const uint32_t offV = (uint32_t)(((lane & 15) * 72 + (lane >> 4) * 8) * 2);

    float m0v = -1e30f, m1v = -1e30f, l0 = 0.f, l1 = 0.f;
    float o[8][4];
#pragma unroll
    for (int nd = 0; nd < 8; nd++)
#pragma unroll
        for (int q = 0; q < 4; q++) o[nd][q] = 0.f;

    load_kv(0, 0);
    CP_COMMIT();

    for (int t = 0; t < 128; t++) {
        if (t + 1 < 128) {
            load_kv(t + 1, (t + 1) & 1);
            CP_COMMIT();
            asm volatile("cp.async.wait_group 1;");
        } else {
            asm volatile("cp.async.wait_group 0;");
        }
        __syncthreads();
        const uint32_t kb = sbase + (t & 1) * 18432;

        // ---- S = Q @ K^T (Q pre-scaled) : 16 rows x 32 keys per warp
        float s[4][4];
#pragma unroll
        for (int ni = 0; ni < 4; ni++)
#pragma unroll
            for (int q = 0; q < 4; q++) s[ni][q] = 0.f;
#pragma unroll
        for (int j = 0; j < 4; j++) {
            uint32_t bh[4], bl[4];
            LDSM4(bh, kb + offK + j * 32);                 // keys 0-15
            LDSM4(bl, kb + 4608 + offK + j * 32);
            MMA_BF16(s[0], fqh[j], bh[0], bh[1]);
            MMA_BF16(s[0], fql[j], bh[0], bh[1]);
            MMA_BF16(s[0], fqh[j], bl[0], bl[1]);
            MMA_BF16(s[1], fqh[j], bh[2], bh[3]);
            MMA_BF16(s[1], fql[j], bh[2], bh[3]);
            MMA_BF16(s[1], fqh[j], bl[2], bl[3]);
            uint32_t ch[4], cl[4];
            LDSM4(ch, kb + offK + 2304 + j * 32);          // keys 16-31
            LDSM4(cl, kb + 4608 + offK + 2304 + j * 32);
            MMA_BF16(s[2], fqh[j], ch[0], ch[1]);
            MMA_BF16(s[2], fql[j], ch[0], ch[1]);
            MMA_BF16(s[2], fqh[j], cl[0], cl[1]);
            MMA_BF16(s[3], fqh[j], ch[2], ch[3]);
            MMA_BF16(s[3], fql[j], ch[2], ch[3]);
            MMA_BF16(s[3], fqh[j], cl[2], cl[3]);
        }

        // ---- online softmax (rows g and g+8; each row spread over 4 lanes)
        float ml0 = -1e30f, ml1 = -1e30f;
#pragma unroll
        for (int ni = 0; ni < 4; ni++) {
            ml0 = fmaxf(ml0, fmaxf(s[ni][0], s[ni][1]));
            ml1 = fmaxf(ml1, fmaxf(s[ni][2], s[ni][3]));
        }
        ml0 = fmaxf(ml0, __shfl_xor_sync(0xffffffffu, ml0, 1));
        ml0 = fmaxf(ml0, __shfl_xor_sync(0xffffffffu, ml0, 2));
        ml1 = fmaxf(ml1, __shfl_xor_sync(0xffffffffu, ml1, 1));
        ml1 = fmaxf(ml1, __shfl_xor_sync(0xffffffffu, ml1, 2));
        float mn0 = fmaxf(m0v, ml0), mn1 = fmaxf(m1v, ml1);
        float c0 = __expf(m0v - mn0), c1 = __expf(m1v - mn1);
        m0v = mn0; m1v = mn1;
        float rs0 = 0.f, rs1 = 0.f;
#pragma unroll
        for (int ni = 0; ni < 4; ni++) {
            s[ni][0] = __expf(s[ni][0] - mn0); rs0 += s[ni][0];
            s[ni][1] = __expf(s[ni][1] - mn0); rs0 += s[ni][1];
            s[ni][2] = __expf(s[ni][2] - mn1); rs1 += s[ni][2];
            s[ni][3] = __expf(s[ni][3] - mn1); rs1 += s[ni][3];
        }
        rs0 += __shfl_xor_sync(0xffffffffu, rs0, 1);
        rs0 += __shfl_xor_sync(0xffffffffu, rs0, 2);
        rs1 += __shfl_xor_sync(0xffffffffu, rs1, 1);
        rs1 += __shfl_xor_sync(0xffffffffu, rs1, 2);
        l0 = l0 * c0 + rs0;
        l1 = l1 * c1 + rs1;
#pragma unroll
        for (int nd = 0; nd < 8; nd++) {
            o[nd][0] *= c0; o[nd][1] *= c0;
            o[nd][2] *= c1; o[nd][3] *= c1;
        }

        // ---- O += P @ V  (P dual-plane from registers, V via ldmatrix.trans)
#pragma unroll
        for (int c = 0; c < 2; c++) {
            uint32_t ah[4], al[4];
            splitpk(s[2 * c][0],     s[2 * c][1],     ah[0], al[0]);
            splitpk(s[2 * c][2],     s[2 * c][3],     ah[1], al[1]);
            splitpk(s[2 * c + 1][0], s[2 * c + 1][1], ah[2], al[2]);
            splitpk(s[2 * c + 1][2], s[2 * c + 1][3], ah[3], al[3]);
#pragma unroll
            for (int gg = 0; gg < 4; gg++) {
                uint32_t vh4[4], vl4[4];
                LDSM4T(vh4, kb + 9216 + offV + c * 2304 + gg * 32);
                LDSM4T(vl4, kb + 13824 + offV + c * 2304 + gg * 32);
                MMA_BF16(o[2 * gg],     ah, vh4[0], vh4[1]);
                MMA_BF16(o[2 * gg],     al, vh4[0], vh4[1]);
                MMA_BF16(o[2 * gg],     ah, vl4[0], vl4[1]);
                MMA_BF16(o[2 * gg + 1], ah, vh4[2], vh4[3]);
                MMA_BF16(o[2 * gg + 1], al, vh4[2], vh4[3]);
                MMA_BF16(o[2 * gg + 1], ah, vl4[2], vl4[3]);
            }
        }
        __syncthreads();
    }

    // ---- normalize + store (dual-plane)
    float i0 = 1.f / l0, i1 = 1.f / l1;
#pragma unroll
    for (int nd = 0; nd < 8; nd++) {
        int col = h * 64 + nd * 8 + tig * 2;
        long r0 = (long)(q0 + w * 16 + g) * 256 + col;
        long r1 = (long)(q0 + w * 16 + g + 8) * 256 + col;
        split2st(o[nd][0] * i0, o[nd][1] * i0, Oh, Ol, r0);
        split2st(o[nd][2] * i1, o[nd][3] * i1, Oh, Ol, r1);
    }
}

// ---------------- conversions ---------------------------------------------
__global__ void conv_k(const float* __restrict__ in, bf16* __restrict__ oh,
                       bf16* __restrict__ ol, int n)
{
    int i = blockIdx.x * 256 + threadIdx.x;
    if (i < n) split1(in[i], oh, ol, i);
}

__global__ void convT_k(const float* __restrict__ in, bf16* __restrict__ oh,
                        bf16* __restrict__ ol, int K, int N)
{
    __shared__ float tile[32][33];
    const int k0 = blockIdx.y * 32, n0 = blockIdx.x * 32;
    const int tx = threadIdx.x, ty = threadIdx.y;
#pragma unroll
    for (int p = 0; p < 4; p++)
        tile[ty + p * 8][tx] = in[(long)(k0 + ty + p * 8) * N + n0 + tx];
    __syncthreads();
#pragma unroll
    for (int p = 0; p < 4; p++) {
        int n = n0 + ty + p * 8, k = k0 + tx;
        split1(tile[tx][ty + p * 8], oh, ol, (long)n * K + k);
    }
}

// ---------------- top-16 per row (packed u64 warp-shuffle reduction) ------
// packed = (float_bits(v) << 32) | ~idx  with v >= 0 -> u64 max == (greater v,
// then smaller idx) exactly. Self/cleared entries get packed = 0 (never win).
__global__ void __launch_bounds__(256) topk_kernel(const bf16* __restrict__ Sh,
                                                   const bf16* __restrict__ Sl,
                                                   int* __restrict__ idx)
{
    const int row = blockIdx.x, t = threadIdx.x;
    const int lane = t & 31, warp = t >> 5;
    unsigned long long lv[16];
#pragma unroll
    for (int i = 0; i < 16; i++) {
        int j = i * 256 + t;
        float v = fmaxf(rec(Sh, Sl, (long)row * NN + j), 0.f);
        unsigned long long p =
            ((unsigned long long)__float_as_uint(v) << 32) | (unsigned)(~j);
        if (j == row) p = 0ull;
        lv[i] = p;
    }
    __shared__ unsigned long long sw[8];
    for (int r = 0; r < 16; r++) {
        unsigned long long best = lv[0];
#pragma unroll
        for (int i = 1; i < 16; i++) best = best > lv[i] ? best : lv[i];
#pragma unroll
        for (int m = 16; m; m >>= 1) {
            unsigned long long o = __shfl_xor_sync(0xffffffffu, best, m);
            best = best > o ? best : o;
        }
        if (lane == 0) sw[warp] = best;
        __syncthreads();
        unsigned long long w0 = sw[0];
#pragma unroll
        for (int q = 1; q < 8; q++) w0 = w0 > sw[q] ? w0 : sw[q];
        int winj = (int)(~(unsigned)(w0 & 0xFFFFFFFFull));
        if (t == 0) idx[row * 16 + r] = winj;
        if ((winj & 255) == t) lv[winj >> 8] = 0ull;
        __syncthreads();
    }
}

// ---------------- GAT score precompute ------------------------------------
__global__ void __launch_bounds__(256) gat_scores(const bf16* __restrict__ hh,
                                                  const bf16* __restrict__ hl,
                                                  const float* __restrict__ a_s,
                                                  const float* __restrict__ a_d,
                                                  float* __restrict__ ssrc,
                                                  float* __restrict__ sdst,
                                                  int heads)
{
    const int n = blockIdx.x, t = threadIdx.x;
    float hv = rec(hh, hl, (long)n * 256 + t);
    float ps = hv * a_s[t];
    float pd = hv * a_d[t];
#pragma unroll
    for (int m = 16; m; m >>= 1) {
        ps += __shfl_xor_sync(0xffffffffu, ps, m);
        pd += __shfl_xor_sync(0xffffffffu, pd, m);
    }
    __shared__ float ws[8], wd[8];
    if ((t & 31) == 0) { ws[t >> 5] = ps; wd[t >> 5] = pd; }
    __syncthreads();
    if (t < heads) {
        int wph = 8 / heads;
        float s = 0.f, d = 0.f;
        for (int w = 0; w < wph; w++) { s += ws[t * wph + w]; d += wd[t * wph + w]; }
        ssrc[n * heads + t] = s;
        sdst[n * heads + t] = d;
    }
}

// ---------------- GAT aggregation (17 in-edges per dst) -------------------
template<int HEADS>
__global__ void __launch_bounds__(256) gat_agg(const bf16* __restrict__ hh,
                                               const bf16* __restrict__ hl,
                                               const float* __restrict__ ssrc,
                                               const float* __restrict__ sdst,
                                               const int* __restrict__ idx,
                                               const float* __restrict__ bias,
                                               bf16* __restrict__ oh,
                                               bf16* __restrict__ ol,
                                               float* __restrict__ o32,
                                               int do_relu)
{
    const int i = blockIdx.x, t = threadIdx.x;
    __shared__ int   s_src[17];
    __shared__ float s_e[HEADS * 17];
    __shared__ float s_a[HEADS * 17];
    if (t < 16) s_src[t] = idx[i * 16 + t];
    if (t == 16) s_src[16] = i;
    __syncthreads();
    if (t < HEADS * 17) {
        int hh2 = t / 17, j = t % 17;
        float e = ssrc[s_src[j] * HEADS + hh2] + sdst[i * HEADS + hh2];
        s_e[t] = e > 0.f ? e : 0.2f * e;
    }
    __syncthreads();
    if (t < HEADS) {
        float m = -1e30f;
        for (int j = 0; j < 17; j++) m = fmaxf(m, s_e[t * 17 + j]);
        float s = 0.f;
        for (int j = 0; j < 17; j++) {
            float p = __expf(s_e[t * 17 + j] - m);
            s_a[t * 17 + j] = p; s += p;
        }
        float inv = 1.f / s;
        for (int j = 0; j < 17; j++) s_a[t * 17 + j] *= inv;
    }
    __syncthreads();
    const int hd = t / (256 / HEADS);
    float acc = 0.f;
#pragma unroll
    for (int j = 0; j < 17; j++)
        acc = fmaf(s_a[hd * 17 + j], rec(hh, hl, (long)s_src[j] * 256 + t), acc);
    float o = acc + bias[t];
    if (do_relu) o = fmaxf(o, 0.f);
    if (oh) split1(o, oh, ol, (long)i * 256 + t);
    else    o32[(long)i * 256 + t] = o;
}

// ---------------- residual + LayerNorm, dual-plane ------------------------
__global__ void __launch_bounds__(256) add_ln_kernel(const bf16* __restrict__ xh,
                                                     const bf16* __restrict__ xl,
                                                     const bf16* __restrict__ th,
                                                     const bf16* __restrict__ tl,
                                                     const float* __restrict__ g,
                                                     const float* __restrict__ b,
                                                     bf16* __restrict__ oh,
                                                     bf16* __restrict__ ol)
{
    const int n = blockIdx.x, t = threadIdx.x;
    const long off = (long)n * 256 + t;
    float v = rec(xh, xl, off) + rec(th, tl, off);
    __shared__ float red[8];
    float s = v;
#pragma unroll
    for (int m = 16; m; m >>= 1) s += __shfl_xor_sync(0xffffffffu, s, m);
    if ((t & 31) == 0) red[t >> 5] = s;
    __syncthreads();
    float tot = 0.f;
#pragma unroll
    for (int w = 0; w < 8; w++) tot += red[w];
    float mu = tot * (1.f / 256.f);
    float d = v - mu;
    float sq = d * d;
#pragma unroll
    for (int m = 16; m; m >>= 1) sq += __shfl_xor_sync(0xffffffffu, sq, m);
    __syncthreads();
    if ((t & 31) == 0) red[t >> 5] = sq;
    __syncthreads();
    float tv = 0.f;
#pragma unroll
    for (int w = 0; w < 8; w++) tv += red[w];
    float var = tv * (1.f / 256.f);
    split1(d * rsqrtf(var + 1e-5f) * g[t] + b[t], oh, ol, off);
}

// ---------------- transpose [4096,256] fp32 -> [256,4096] -----------------
__global__ void transpose_kernel(const float* __restrict__ in, float* __restrict__ out)
{
    __shared__ float tile[32][33];
    const int bx = blockIdx.x * 32, by = blockIdx.y * 32;
    const int tx = threadIdx.x, ty = threadIdx.y;
#pragma unroll
    for (int p = 0; p < 4; p++)
        tile[ty + p * 8][tx] = in[(long)(by + ty + p * 8) * 256 + bx + tx];
    __syncthreads();
#pragma unroll
    for (int p = 0; p < 4; p++)
        out[(long)(bx + ty + p * 8) * 4096 + by + tx] = tile[tx][ty + p * 8];
}

// ---------------- launch ---------------------------------------------------
extern "C" void kernel_launch(void* const* d_in, const int* in_sizes, int n_in,
                              void* d_out, int out_size)
{
    const float* window   = (const float*)d_in[0];
    const float* gl_w     = (const float*)d_in[1];
    const float* gl_b     = (const float*)d_in[2];
    const float* enc_W    = (const float*)d_in[3];
    const float* enc_asrc = (const float*)d_in[4];
    const float* enc_adst = (const float*)d_in[5];
    const float* enc_b    = (const float*)d_in[6];
    const float* tr_wqkv  = (const float*)d_in[7];
    const float* tr_bqkv  = (const float*)d_in[8];
    const float* tr_wo    = (const float*)d_in[9];
    const float* tr_bo    = (const float*)d_in[10];
    const float* ln1g     = (const float*)d_in[11];
    const float* ln1b     = (const float*)d_in[12];
    const float* tr_w1    = (const float*)d_in[13];
    const float* tr_b1    = (const float*)d_in[14];
    const float* tr_w2    = (const float*)d_in[15];
    const float* tr_b2    = (const float*)d_in[16];
    const float* ln2g     = (const float*)d_in[17];
    const float* ln2b     = (const float*)d_in[18];
    const float* skip_w   = (const float*)d_in[19];
    const float* skip_b   = (const float*)d_in[20];
    const float* dec_W    = (const float*)d_in[21];
    const float* dec_asrc = (const float*)d_in[22];
    const float* dec_adst = (const float*)d_in[23];
    const float* dec_b    = (const float*)d_in[24];
    const float* dec_lW   = (const float*)d_in[25];
    const float* dec_lasrc= (const float*)d_in[26];
    const float* dec_ladst= (const float*)d_in[27];
    const float* dec_lb   = (const float*)d_in[28];

    bf16 *winh, *winl, *h0h, *h0l, *xh, *xl, *yh, *yl, *th, *tl;
    bf16 *qkvh, *qkvl, *ffh, *ffl, *simh, *siml, *wh, *wl;
    float *tb, *ssrc, *sdst;
    int* idxb;
    cudaGetSymbolAddress((void**)&winh, g_win_h); cudaGetSymbolAddress((void**)&winl, g_win_l);
    cudaGetSymbolAddress((void**)&h0h,  g_h0_h);  cudaGetSymbolAddress((void**)&h0l,  g_h0_l);
    cudaGetSymbolAddress((void**)&xh,   g_x_h);   cudaGetSymbolAddress((void**)&xl,   g_x_l);
    cudaGetSymbolAddress((void**)&yh,   g_y_h);   cudaGetSymbolAddress((void**)&yl,   g_y_l);
    cudaGetSymbolAddress((void**)&th,   g_t_h);   cudaGetSymbolAddress((void**)&tl,   g_t_l);
    cudaGetSymbolAddress((void**)&qkvh, g_qkv_h); cudaGetSymbolAddress((void**)&qkvl, g_qkv_l);
    cudaGetSymbolAddress((void**)&ffh,  g_ff_h);  cudaGetSymbolAddress((void**)&ffl,  g_ff_l);
    cudaGetSymbolAddress((void**)&simh, g_sim_h); cudaGetSymbolAddress((void**)&siml, g_sim_l);
    cudaGetSymbolAddress((void**)&wh,   g_w_h);   cudaGetSymbolAddress((void**)&wl,   g_w_l);
    cudaGetSymbolAddress((void**)&tb,   g_tb);
    cudaGetSymbolAddress((void**)&ssrc, g_ssrc);  cudaGetSymbolAddress((void**)&sdst, g_sdst);
    cudaGetSymbolAddress((void**)&idxb, g_idx);

    const long O_GLW = 0,       O_ENCW = 65536,  O_WQKV = 262144, O_WO = 655360;
    const long O_W1 = 786432,   O_W2 = 1048576,  O_SKIP = 1310720;
    const long O_DECW = 1376256, O_DECL = 1507328;

    dim3 blk(256), tblk(32, 8);

    // ---- input + weight conversion to dual-plane bf16 (separate launches) ----
    conv_k<<<NN * DD / 256, blk>>>(window, winh, winl, NN * DD);
    convT_k<<<dim3(8, 8), tblk>>>(gl_w, wh + O_GLW, wl + O_GLW, 256, 256);
    for (int i = 0; i < 3; i++)
        convT_k<<<dim3(8, 8), tblk>>>(enc_W + (long)i * 65536, wh + O_ENCW + i * 65536,
                                      wl + O_ENCW + i * 65536, 256, 256);
    for (int i = 0; i < 2; i++) {
        conv_k<<<768, blk>>>(tr_wqkv + (long)i * 196608, wh + O_WQKV + i * 196608,
                             wl + O_WQKV + i * 196608, 196608);
        conv_k<<<256, blk>>>(tr_wo + (long)i * 65536, wh + O_WO + i * 65536,
                             wl + O_WO + i * 65536, 65536);
        convT_k<<<dim3(16, 8), tblk>>>(tr_w1 + (long)i * 131072, wh + O_W1 + i * 131072,
                                       wl + O_W1 + i * 131072, 256, 512);
        convT_k<<<dim3(8, 16), tblk>>>(tr_w2 + (long)i * 131072, wh + O_W2 + i * 131072,
                                       wl + O_W2 + i * 131072, 512, 256);
        convT_k<<<dim3(8, 8), tblk>>>(dec_W + (long)i * 65536, wh + O_DECW + i * 65536,
                                      wl + O_DECW + i * 65536, 256, 256);
    }
    convT_k<<<dim3(8, 8), tblk>>>(skip_w, wh + O_SKIP, wl + O_SKIP, 256, 256);
    convT_k<<<dim3(8, 8), tblk>>>(dec_lW, wh + O_DECL, wl + O_DECL, 256, 256);

    // ---- graph learning: h0 = tanh(win @ glW + b); sim = h0 @ h0^T; top-16
    gemm_bf3<64, 2><<<dim3(4, 32), blk>>>(winh, winl, DD, wh + O_GLW, wl + O_GLW, DD,
        gl_b, h0h, h0l, DD, DD, 0, 0, 0, 1.f);
    gemm_bf3<128, 0><<<dim3(32, 32), blk>>>(h0h, h0l, DD, h0h, h0l, DD,
        nullptr, simh, siml, NN, DD, 0, 0, 0, 1.f);
    topk_kernel<<<NN, blk>>>(simh, siml, idxb);

    // ---- encoder: 3x GAT(4 heads) + relu
    const bf16* xih = winh; const bf16* xil = winl;
    for (int i = 0; i < 3; i++) {
        gemm_bf3<64, 0><<<dim3(4, 32), blk>>>(xih, xil, DD,
            wh + O_ENCW + i * 65536, wl + O_ENCW + i * 65536, DD,
            nullptr, yh, yl, DD, DD, 0, 0, 0, 1.f);
        gat_scores<<<NN, blk>>>(yh, yl, enc_asrc + i * 256, enc_adst + i * 256, ssrc, sdst, 4);
        gat_agg<4><<<NN, blk>>>(yh, yl, ssrc, sdst, idxb, enc_b + i * DD, xh, xl, nullptr, 1);
        xih = xh; xil = xl;
    }

    // ---- transformer bottleneck: 2 layers (fused flash attention)
    for (int i = 0; i < 2; i++) {
        // qkv = x @ wqkv^T + bqkv, Q columns pre-scaled by 1/8 (ACT=4)
        gemm_bf3<128, 4><<<dim3(6, 32), blk>>>(xh, xl, DD,
            wh + O_WQKV + i * 196608, wl + O_WQKV + i * 196608, DD,
            tr_bqkv + i * 768, qkvh, qkvl, 768, DD, 0, 0, 0, 1.f);
        flash_attn<<<dim3(32, 4), blk>>>(qkvh, qkvl, yh, yl);
        gemm_bf3<64, 0><<<dim3(4, 32), blk>>>(yh, yl, DD,
            wh + O_WO + i * 65536, wl + O_WO + i * 65536, DD,
            tr_bo + i * DD, th, tl, DD, DD, 0, 0, 0, 1.f);
        add_ln_kernel<<<NN, blk>>>(xh, xl, th, tl, ln1g + i * DD, ln1b + i * DD, xh, xl);
        gemm_bf3<128, 1><<<dim3(4, 32), blk>>>(xh, xl, DD,
            wh + O_W1 + i * 131072, wl + O_W1 + i * 131072, DD,
            tr_b1 + i * 512, ffh, ffl, 512, DD, 0, 0, 0, 1.f);
        gemm_bf3<64, 0><<<dim3(4, 32), blk>>>(ffh, ffl, 512,
            wh + O_W2 + i * 131072, wl + O_W2 + i * 131072, 512,
            tr_b2 + i * DD, th, tl, DD, 512, 0, 0, 0, 1.f);
        add_ln_kernel<<<NN, blk>>>(xh, xl, th, tl, ln2g + i * DD, ln2b + i * DD, xh, xl);
    }

    // ---- skip connection fused into GEMM (ACT=3: C += window @ skip_w + b)
    gemm_bf3<64, 3><<<dim3(4, 32), blk>>>(winh, winl, DD, wh + O_SKIP, wl + O_SKIP, DD,
        skip_b, xh, xl, DD, DD, 0, 0, 0, 1.f);

    // ---- decoder: 2x GAT(4 heads)+relu, then single-head GAT
    for (int i = 0; i < 2; i++) {
        gemm_bf3<64, 0><<<dim3(4, 32), blk>>>(xh, xl, DD,
            wh + O_DECW + i * 65536, wl + O_DECW + i * 65536, DD,
            nullptr, yh, yl, DD, DD, 0, 0, 0, 1.f);
        gat_scores<<<NN, blk>>>(yh, yl, dec_asrc + i * 256, dec_adst + i * 256, ssrc, sdst, 4);
        gat_agg<4><<<NN, blk>>>(yh, yl, ssrc, sdst, idxb, dec_b + i * DD, xh, xl, nullptr, 1);
    }
    gemm_bf3<64, 0><<<dim3(4, 32), blk>>>(xh, xl, DD, wh + O_DECL, wl + O_DECL, DD,
        nullptr, yh, yl, DD, DD, 0, 0, 0, 1.f);
    gat_scores<<<NN, blk>>>(yh, yl, dec_lasrc, dec_ladst, ssrc, sdst, 1);
    gat_agg<1><<<NN, blk>>>(yh, yl, ssrc, sdst, idxb, dec_lb, nullptr, nullptr, tb, 0);

    // ---- output: transpose to [256, 4096]
    transpose_kernel<<<dim3(8, 128), dim3(32, 8)>>>(tb, (float*)d_out);
}

// round 14
// speedup vs baseline: 1.0347x; 1.0347x over previous
#include <cuda_runtime.h>
#include <cuda_bf16.h>
#include <math.h>
#include <stdint.h>

typedef __nv_bfloat16 bf16;

#define NN 4096
#define DD 256

// ---------------- scratch (device globals; no allocation) ----------------
__device__ bf16 g_win_h[NN * DD], g_win_l[NN * DD];
__device__ bf16 g_h0_h[NN * DD],  g_h0_l[NN * DD];
__device__ bf16 g_x_h[NN * DD],   g_x_l[NN * DD];
__device__ bf16 g_y_h[NN * DD],   g_y_l[NN * DD];
__device__ bf16 g_t_h[NN * DD],   g_t_l[NN * DD];
__device__ bf16 g_qkv_h[NN * 768], g_qkv_l[NN * 768];
__device__ bf16 g_ff_h[NN * 512],  g_ff_l[NN * 512];
__device__ bf16 g_sim_h[(long)NN * NN], g_sim_l[(long)NN * NN];   // 32MB each
#define WPOOL 1572864
__device__ bf16 g_w_h[WPOOL], g_w_l[WPOOL];
__device__ float g_tb[NN * DD];
__device__ float g_ssrc[NN * 4], g_sdst[NN * 4];
__device__ int   g_idx[NN * 16];

// ---------------- helpers -------------------------------------------------
__device__ __forceinline__ void cp16(uint32_t dst, const void* src) {
    asm volatile("cp.async.cg.shared.global [%0], [%1], 16;" :: "r"(dst), "l"(src));
}
#define CP_COMMIT() asm volatile("cp.async.commit_group;")

__device__ __forceinline__ float rec(const bf16* H, const bf16* L, long i) {
    return __bfloat162float(H[i]) + __bfloat162float(L[i]);
}
__device__ __forceinline__ void split1(float v, bf16* H, bf16* L, long off) {
    bf16 h = __float2bfloat16(v);
    H[off] = h;
    L[off] = __float2bfloat16(v - __bfloat162float(h));
}
__device__ __forceinline__ uint32_t pk(bf16 a, bf16 b) {
    __nv_bfloat162 t = __halves2bfloat162(a, b);
    return *(uint32_t*)&t;
}
__device__ __forceinline__ uint32_t pkf(float lo_v, float hi_v) {
    uint32_t r;   // pack bf16(lo_v) into low half, bf16(hi_v) into high half
    asm("cvt.rn.bf16x2.f32 %0, %1, %2;" : "=r"(r) : "f"(hi_v), "f"(lo_v));
    return r;
}
__device__ __forceinline__ void split2st(float v0, float v1, bf16* H, bf16* L, long off) {
    bf16 h0 = __float2bfloat16(v0), h1 = __float2bfloat16(v1);
    float r0 = v0 - __bfloat162float(h0), r1 = v1 - __bfloat162float(h1);
    *(uint32_t*)(H + off) = pk(h0, h1);
    *(uint32_t*)(L + off) = pk(__float2bfloat16(r0), __float2bfloat16(r1));
}
// Truncation split (P path only): hi = bitwise truncate (exact residual in fp32)
__device__ __forceinline__ void splitpk(float v0, float v1, uint32_t& hi, uint32_t& lo) {
    uint32_t u0 = __float_as_uint(v0) & 0xFFFF0000u;
    uint32_t u1 = __float_as_uint(v1) & 0xFFFF0000u;
    hi = (u0 >> 16) | u1;
    lo = pkf(v0 - __uint_as_float(u0), v1 - __uint_as_float(u1));
}
__device__ __forceinline__ float ex2(float x) {
    float r; asm("ex2.approx.f32 %0, %1;" : "=f"(r) : "f"(x)); return r;
}

#define MMA_BF16(c, a, b0, b1) \
    asm volatile("mma.sync.aligned.m16n8k16.row.col.f32.bf16.bf16.f32 " \
                 "{%0,%1,%2,%3},{%4,%5,%6,%7},{%8,%9},{%0,%1,%2,%3};" \
                 : "+f"((c)[0]), "+f"((c)[1]), "+f"((c)[2]), "+f"((c)[3]) \
                 : "r"((a)[0]), "r"((a)[1]), "r"((a)[2]), "r"((a)[3]), \
                   "r"(b0), "r"(b1))

#define LDSM4(r, addr) \
    asm volatile("ldmatrix.sync.aligned.m8n8.x4.shared.b16 {%0,%1,%2,%3}, [%4];" \
                 : "=r"((r)[0]), "=r"((r)[1]), "=r"((r)[2]), "=r"((r)[3]) \
                 : "r"(addr))

#define LDSM4T(r, addr) \
    asm volatile("ldmatrix.sync.aligned.m8n8.x4.trans.shared.b16 {%0,%1,%2,%3}, [%4];" \
                 : "=r"((r)[0]), "=r"((r)[1]), "=r"((r)[2]), "=r"((r)[3]) \
                 : "r"(addr))

// ---------------- split-bf16 3-product GEMM (both operands k-major) -------
// ACT: 0 none, 1 relu, 2 tanh, 3 accumulate-into-C, 4 qkv (scale cols<256 by log2e/8)
template<int BN, int ACT>
__global__ void __launch_bounds__(256) gemm_bf3(
    const bf16* __restrict__ Ah, const bf16* __restrict__ Al, int lda,
    const bf16* __restrict__ Bh, const bf16* __restrict__ Bl, int ldb,
    const float* __restrict__ bias,
    bf16* __restrict__ Ch, bf16* __restrict__ Cl, int ldc,
    int K, long sAz, long sBz, long sCz, float alpha)
{
    constexpr int NI = BN / 32;
    __shared__ bf16 sAh[2][128 * 24], sAl[2][128 * 24];
    __shared__ bf16 sBh[2][BN * 24],  sBl[2][BN * 24];

    const int tid = threadIdx.x;
    const int warp = tid >> 5, lane = tid & 31;
    const int g = lane >> 2, tig = lane & 3;
    const int wm = warp & 1, wn = warp >> 1;
    const int wm0 = wm * 64, wn0 = wn * (BN / 4);
    const int bm = blockIdx.y * 128, bn = blockIdx.x * BN;
    const long z = blockIdx.z;
    Ah += z * sAz; Al += z * sAz;
    Bh += z * sBz; Bl += z * sBz;
    Ch += z * sCz; Cl += z * sCz;

    const uint32_t offA = (uint32_t)(((wm0 + (lane & 15)) * 24 + (lane >> 4) * 8) * 2);
    const uint32_t offB = (uint32_t)(((wn0 + ((lane >> 4) & 1) * 8 + (lane & 7)) * 24
                                      + ((lane >> 3) & 1) * 8) * 2);
    uint32_t bAh[2] = { (uint32_t)__cvta_generic_to_shared(&sAh[0][0]),
                        (uint32_t)__cvta_generic_to_shared(&sAh[1][0]) };
    uint32_t bAl[2] = { (uint32_t)__cvta_generic_to_shared(&sAl[0][0]),
                        (uint32_t)__cvta_generic_to_shared(&sAl[1][0]) };
    uint32_t bBh[2] = { (uint32_t)__cvta_generic_to_shared(&sBh[0][0]),
                        (uint32_t)__cvta_generic_to_shared(&sBh[1][0]) };
    uint32_t bBl[2] = { (uint32_t)__cvta_generic_to_shared(&sBl[0][0]),
                        (uint32_t)__cvta_generic_to_shared(&sBl[1][0]) };

    float acc[4][NI][4];
#pragma unroll
    for (int mi = 0; mi < 4; mi++)
#pragma unroll
        for (int ni = 0; ni < NI; ni++)
#pragma unroll
            for (int q = 0; q < 4; q++) acc[mi][ni][q] = 0.f;

    auto load_tile = [&](int t, int buf) {
        const int k0 = t * 16;
        {
            int row = tid >> 1, half = tid & 1;
            uint32_t off = (uint32_t)(row * 24 + half * 8) * 2;
            long src = (long)(bm + row) * lda + k0 + half * 8;
            cp16(bAh[buf] + off, Ah + src);
            cp16(bAl[buf] + off, Al + src);
        }
        if (BN == 128 || tid < BN * 2) {
            int row = tid >> 1, half = tid & 1;
            uint32_t off = (uint32_t)(row * 24 + half * 8) * 2;
            long src = (long)(bn + row) * ldb + k0 + half * 8;
            cp16(bBh[buf] + off, Bh + src);
            cp16(bBl[buf] + off, Bl + src);
        }
    };

    load_tile(0, 0);
    CP_COMMIT();
    const int nt = K / 16;

    for (int t = 0; t < nt; t++) {
        if (t + 1 < nt) {
            load_tile(t + 1, (t + 1) & 1);
            CP_COMMIT();
            asm volatile("cp.async.wait_group 1;");
        } else {
            asm volatile("cp.async.wait_group 0;");
        }
        __syncthreads();
        const int buf = t & 1;

        uint32_t fah[4][4], fal[4][4];
#pragma unroll
        for (int mi = 0; mi < 4; mi++) {
            LDSM4(fah[mi], bAh[buf] + offA + mi * 768);
            LDSM4(fal[mi], bAl[buf] + offA + mi * 768);
        }
        uint32_t bh[NI][2], bl[NI][2];
#pragma unroll
        for (int pi = 0; pi < NI / 2; pi++) {
            LDSM4(bh[2 * pi], bBh[buf] + offB + pi * 768);
            LDSM4(bl[2 * pi], bBl[buf] + offB + pi * 768);
        }
#pragma unroll
        for (int ni = 0; ni < NI; ni++) {
#pragma unroll
            for (int mi = 0; mi < 4; mi++) {
                MMA_BF16(acc[mi][ni], fah[mi], bh[ni][0], bh[ni][1]);
                MMA_BF16(acc[mi][ni], fal[mi], bh[ni][0], bh[ni][1]);
                MMA_BF16(acc[mi][ni], fah[mi], bl[ni][0], bl[ni][1]);
            }
        }
        __syncthreads();
    }

#pragma unroll
    for (int mi = 0; mi < 4; mi++) {
#pragma unroll
        for (int ni = 0; ni < NI; ni++) {
            int col = bn + wn0 + ni * 8 + tig * 2;
            float b0 = 0.f, b1 = 0.f;
            if (bias) { b0 = bias[col]; b1 = bias[col + 1]; }
#pragma unroll
            for (int h2 = 0; h2 < 2; h2++) {
                int row = bm + wm0 + mi * 16 + g + h2 * 8;
                long off = (long)row * ldc + col;
                float v0 = acc[mi][ni][h2 * 2 + 0] * alpha + b0;
                float v1 = acc[mi][ni][h2 * 2 + 1] * alpha + b1;
                if (ACT == 1) { v0 = fmaxf(v0, 0.f); v1 = fmaxf(v1, 0.f); }
                if (ACT == 2) { v0 = tanhf(v0); v1 = tanhf(v1); }
                if (ACT == 3) { v0 += rec(Ch, Cl, off); v1 += rec(Ch, Cl, off + 1); }
                if (ACT == 4 && col < 256) { v0 *= 0.18033688011112042f; v1 *= 0.18033688011112042f; }
                split2st(v0, v1, Ch, Cl, off);
            }
        }
    }
}

// ---------------- fused flash attention (bf3, dual-plane P) ---------------
// grid (32, 4): 128 q-rows per block, head = blockIdx.y. 8 warps * 16 rows.
// Q pre-scaled by log2e/8 -> softmax entirely in base 2 (bare ex2.approx).
__global__ void __launch_bounds__(256) flash_attn(
    const bf16* __restrict__ Qh, const bf16* __restrict__ Ql,
    bf16* __restrict__ Oh, bf16* __restrict__ Ol)
{
    __shared__ char smem[2 * 18432];   // Q staging, then KV double buffer
    const int tid = threadIdx.x, lane = tid & 31, w = tid >> 5;
    const int g = lane >> 2, tig = lane & 3;
    const int q0 = blockIdx.x * 128;
    const int h = blockIdx.y;
    const uint32_t sbase = (uint32_t)__cvta_generic_to_shared(smem);

    // ---- stage Q tile (128x64, dual plane, stride 72 elems = 144B)
#pragma unroll
    for (int c = tid; c < 1024; c += 256) {
        int row = c >> 3, off = (c & 7) * 8;
        long src = (long)(q0 + row) * 768 + h * 64 + off;
        cp16(sbase + row * 144 + off * 2, Qh + src);
        cp16(sbase + 18432 + row * 144 + off * 2, Ql + src);
    }
    CP_COMMIT();
    asm volatile("cp.async.wait_group 0;");
    __syncthreads();

    uint32_t fqh[4][4], fql[4][4];
    {
        uint32_t offQ = (uint32_t)(((w * 16 + (lane & 15)) * 72 + (lane >> 4) * 8) * 2);
#pragma unroll
        for (int j = 0; j < 4; j++) {
            LDSM4(fqh[j], sbase + offQ + j * 32);
            LDSM4(fql[j], sbase + 18432 + offQ + j * 32);
        }
    }
    __syncthreads();   // Q reads done; smem reused as K/V buffers

    // KV buffer layout per stage (18432B): kh 0 / kl 4608 / vh 9216 / vl 13824
    auto load_kv = [&](int t, int b) {
        uint32_t base = sbase + b * 18432;
        int row = tid >> 3, off = (tid & 7) * 8;
        long key = (long)t * 32 + row;
        long srcK = key * 768 + 256 + h * 64 + off;
        long srcV = key * 768 + 512 + h * 64 + off;
        uint32_t d = row * 144 + off * 2;
        cp16(base + d,         Qh + srcK);
        cp16(base + 4608 + d,  Ql + srcK);
        cp16(base + 9216 + d,  Qh + srcV);
        cp16(base + 13824 + d, Ql + srcV);
    };

    const uint32_t offK = (uint32_t)(((((lane >> 4) & 1) * 8 + (lane & 7)) * 72
                                      + ((lane >> 3) & 1) * 8) * 2);
    const uint32_t offV = (uint32_t)(((lane & 15) * 72 + (lane >> 4) * 8) * 2);

    float m0v = -1e30f, m1v = -1e30f, l0 = 0.f, l1 = 0.f;
    float o[8][4];
#pragma unroll
    for (int nd = 0; nd < 8; nd++)
#pragma unroll
        for (int q = 0; q < 4; q++) o[nd][q] = 0.f;

    load_kv(0, 0);
    CP_COMMIT();

    for (int t = 0; t < 128; t++) {
        if (t + 1 < 128) {
            load_kv(t + 1, (t + 1) & 1);
            CP_COMMIT();
            asm volatile("cp.async.wait_group 1;");
        } else {
            asm volatile("cp.async.wait_group 0;");
        }
        __syncthreads();
        const uint32_t kb = sbase + (t & 1) * 18432;

        // ---- S = Q @ K^T (log2-domain, Q pre-scaled) : 16 rows x 32 keys/warp
        float s[4][4];
#pragma unroll
        for (int ni = 0; ni < 4; ni++)
#pragma unroll
            for (int q = 0; q < 4; q++) s[ni][q] = 0.f;
#pragma unroll
        for (int j = 0; j < 4; j++) {
            uint32_t bh[4], bl[4];
            LDSM4(bh, kb + offK + j * 32);                 // keys 0-15
            LDSM4(bl, kb + 4608 + offK + j * 32);
            MMA_BF16(s[0], fqh[j], bh[0], bh[1]);
            MMA_BF16(s[0], fql[j], bh[0], bh[1]);
            MMA_BF16(s[0], fqh[j], bl[0], bl[1]);
            MMA_BF16(s[1], fqh[j], bh[2], bh[3]);
            MMA_BF16(s[1], fql[j], bh[2], bh[3]);
            MMA_BF16(s[1], fqh[j], bl[2], bl[3]);
            uint32_t ch[4], cl[4];
            LDSM4(ch, kb + offK + 2304 + j * 32);          // keys 16-31
            LDSM4(cl, kb + 4608 + offK + 2304 + j * 32);
            MMA_BF16(s[2], fqh[j], ch[0], ch[1]);
            MMA_BF16(s[2], fql[j], ch[0], ch[1]);
            MMA_BF16(s[2], fqh[j], cl[0], cl[1]);
            MMA_BF16(s[3], fqh[j], ch[2], ch[3]);
            MMA_BF16(s[3], fql[j], ch[2], ch[3]);
            MMA_BF16(s[3], fqh[j], cl[2], cl[3]);
        }

        // ---- online softmax, base 2 (rows g and g+8; row spread over 4 lanes)
        float ml0 = -1e30f, ml1 = -1e30f;
#pragma unroll
        for (int ni = 0; ni < 4; ni++) {
            ml0 = fmaxf(ml0, fmaxf(s[ni][0], s[ni][1]));
            ml1 = fmaxf(ml1, fmaxf(s[ni][2], s[ni][3]));
        }
        ml0 = fmaxf(ml0, __shfl_xor_sync(0xffffffffu, ml0, 1));
        ml0 = fmaxf(ml0, __shfl_xor_sync(0xffffffffu, ml0, 2));
        ml1 = fmaxf(ml1, __shfl_xor_sync(0xffffffffu, ml1, 1));
        ml1 = fmaxf(ml1, __shfl_xor_sync(0xffffffffu, ml1, 2));
        float mn0 = fmaxf(m0v, ml0), mn1 = fmaxf(m1v, ml1);
        float c0 = ex2(m0v - mn0), c1 = ex2(m1v - mn1);
        m0v = mn0; m1v = mn1;
        float rs0 = 0.f, rs1 = 0.f;
#pragma unroll
        for (int ni = 0; ni < 4; ni++) {
            s[ni][0] = ex2(s[ni][0] - mn0); rs0 += s[ni][0];
            s[ni][1] = ex2(s[ni][1] - mn0); rs0 += s[ni][1];
            s[ni][2] = ex2(s[ni][2] - mn1); rs1 += s[ni][2];
            s[ni][3] = ex2(s[ni][3] - mn1); rs1 += s[ni][3];
        }
        rs0 += __shfl_xor_sync(0xffffffffu, rs0, 1);
        rs0 += __shfl_xor_sync(0xffffffffu, rs0, 2);
        rs1 += __shfl_xor_sync(0xffffffffu, rs1, 1);
        rs1 += __shfl_xor_sync(0xffffffffu, rs1, 2);
        l0 = l0 * c0 + rs0;
        l1 = l1 * c1 + rs1;
        if (__any_sync(0xffffffffu, (c0 != 1.f) || (c1 != 1.f))) {
#pragma unroll
            for (int nd = 0; nd < 8; nd++) {
                o[nd][0] *= c0; o[nd][1] *= c0;
                o[nd][2] *= c1; o[nd][3] *= c1;
            }
        }

        // ---- O += P @ V  (P truncation-split in registers, V via ldmatrix.trans)
#pragma unroll
        for (int c = 0; c < 2; c++) {
            uint32_t ah[4], al[4];
            splitpk(s[2 * c][0],     s[2 * c][1],     ah[0], al[0]);
            splitpk(s[2 * c][2],     s[2 * c][3],     ah[1], al[1]);
            splitpk(s[2 * c + 1][0], s[2 * c + 1][1], ah[2], al[2]);
            splitpk(s[2 * c + 1][2], s[2 * c + 1][3], ah[3], al[3]);
#pragma unroll
            for (int gg = 0; gg < 4; gg++) {
                uint32_t vh4[4], vl4[4];
                LDSM4T(vh4, kb + 9216 + offV + c * 2304 + gg * 32);
                LDSM4T(vl4, kb + 13824 + offV + c * 2304 + gg * 32);
                MMA_BF16(o[2 * gg],     ah, vh4[0], vh4[1]);
                MMA_BF16(o[2 * gg],     al, vh4[0], vh4[1]);
                MMA_BF16(o[2 * gg],     ah, vl4[0], vl4[1]);
                MMA_BF16(o[2 * gg + 1], ah, vh4[2], vh4[3]);
                MMA_BF16(o[2 * gg + 1], al, vh4[2], vh4[3]);
                MMA_BF16(o[2 * gg + 1], ah, vl4[2], vl4[3]);
            }
        }
        __syncthreads();
    }

    // ---- normalize + store (dual-plane)
    float i0 = 1.f / l0, i1 = 1.f / l1;
#pragma unroll
    for (int nd = 0; nd < 8; nd++) {
        int col = h * 64 + nd * 8 + tig * 2;
        long r0 = (long)(q0 + w * 16 + g) * 256 + col;
        long r1 = (long)(q0 + w * 16 + g + 8) * 256 + col;
        split2st(o[nd][0] * i0, o[nd][1] * i0, Oh, Ol, r0);
        split2st(o[nd][2] * i1, o[nd][3] * i1, Oh, Ol, r1);
    }
}

// ---------------- conversions (z-batched via blockIdx.z) ------------------
__global__ void conv_k(const float* __restrict__ in, bf16* __restrict__ oh,
                       bf16* __restrict__ ol, int n)
{
    int i = blockIdx.x * 256 + threadIdx.x;
    if (i < n) split1(in[i], oh, ol, i);
}

__global__ void convT_k(const float* __restrict__ in, bf16* __restrict__ oh,
                        bf16* __restrict__ ol, int K, int N)
{
    __shared__ float tile[32][33];
    const long zoff = (long)blockIdx.z * K * N;
    in += zoff; oh += zoff; ol += zoff;
    const int k0 = blockIdx.y * 32, n0 = blockIdx.x * 32;
    const int tx = threadIdx.x, ty = threadIdx.y;
#pragma unroll
    for (int p = 0; p < 4; p++)
        tile[ty + p * 8][tx] = in[(long)(k0 + ty + p * 8) * N + n0 + tx];
    __syncthreads();
#pragma unroll
    for (int p = 0; p < 4; p++) {
        int n = n0 + ty + p * 8, k = k0 + tx;
        split1(tile[tx][ty + p * 8], oh, ol, (long)n * K + k);
    }
}

// ---------------- top-16 per row (packed u64 warp-shuffle reduction) ------
__global__ void __launch_bounds__(256) topk_kernel(const bf16* __restrict__ Sh,
                                                   const bf16* __restrict__ Sl,
                                                   int* __restrict__ idx)
{
    const int row = blockIdx.x, t = threadIdx.x;
    const int lane = t & 31, warp = t >> 5;
    unsigned long long lv[16];
#pragma unroll
    for (int i = 0; i < 16; i++) {
        int j = i * 256 + t;
        float v = fmaxf(rec(Sh, Sl, (long)row * NN + j), 0.f);
        unsigned long long p =
            ((unsigned long long)__float_as_uint(v) << 32) | (unsigned)(~j);
        if (j == row) p = 0ull;
        lv[i] = p;
    }
    __shared__ unsigned long long sw[8];
    for (int r = 0; r < 16; r++) {
        unsigned long long best = lv[0];
#pragma unroll
        for (int i = 1; i < 16; i++) best = best > lv[i] ? best : lv[i];
#pragma unroll
        for (int m = 16; m; m >>= 1) {
            unsigned long long o = __shfl_xor_sync(0xffffffffu, best, m);
            best = best > o ? best : o;
        }
        if (lane == 0) sw[warp] = best;
        __syncthreads();
        unsigned long long w0 = sw[0];
#pragma unroll
        for (int q = 1; q < 8; q++) w0 = w0 > sw[q] ? w0 : sw[q];
        int winj = (int)(~(unsigned)(w0 & 0xFFFFFFFFull));
        if (t == 0) idx[row * 16 + r] = winj;
        if ((winj & 255) == t) lv[winj >> 8] = 0ull;
        __syncthreads();
    }
}

// ---------------- GAT score precompute ------------------------------------
__global__ void __launch_bounds__(256) gat_scores(const bf16* __restrict__ hh,
                                                  const bf16* __restrict__ hl,
                                                  const float* __restrict__ a_s,
                                                  const float* __restrict__ a_d,
                                                  float* __restrict__ ssrc,
                                                  float* __restrict__ sdst,
                                                  int heads)
{
    const int n = blockIdx.x, t = threadIdx.x;
    float hv = rec(hh, hl, (long)n * 256 + t);
    float ps = hv * a_s[t];
    float pd = hv * a_d[t];
#pragma unroll
    for (int m = 16; m; m >>= 1) {
        ps += __shfl_xor_sync(0xffffffffu, ps, m);
        pd += __shfl_xor_sync(0xffffffffu, pd, m);
    }
    __shared__ float ws[8], wd[8];
    if ((t & 31) == 0) { ws[t >> 5] = ps; wd[t >> 5] = pd; }
    __syncthreads();
    if (t < heads) {
        int wph = 8 / heads;
        float s = 0.f, d = 0.f;
        for (int w = 0; w < wph; w++) { s += ws[t * wph + w]; d += wd[t * wph + w]; }
        ssrc[n * heads + t] = s;
        sdst[n * heads + t] = d;
    }
}

// ---------------- GAT aggregation (17 in-edges per dst) -------------------
template<int HEADS>
__global__ void __launch_bounds__(256) gat_agg(const bf16* __restrict__ hh,
                                               const bf16* __restrict__ hl,
                                               const float* __restrict__ ssrc,
                                               const float* __restrict__ sdst,
                                               const int* __restrict__ idx,
                                               const float* __restrict__ bias,
                                               bf16* __restrict__ oh,
                                               bf16* __restrict__ ol,
                                               float* __restrict__ o32,
                                               int do_relu)
{
    const int i = blockIdx.x, t = threadIdx.x;
    __shared__ int   s_src[17];
    __shared__ float s_e[HEADS * 17];
    __shared__ float s_a[HEADS * 17];
    if (t < 16) s_src[t] = idx[i * 16 + t];
    if (t == 16) s_src[16] = i;
    __syncthreads();
    if (t < HEADS * 17) {
        int hh2 = t / 17, j = t % 17;
        float e = ssrc[s_src[j] * HEADS + hh2] + sdst[i * HEADS + hh2];
        s_e[t] = e > 0.f ? e : 0.2f * e;
    }
    __syncthreads();
    if (t < HEADS) {
        float m = -1e30f;
        for (int j = 0; j < 17; j++) m = fmaxf(m, s_e[t * 17 + j]);
        float s = 0.f;
        for (int j = 0; j < 17; j++) {
            float p = __expf(s_e[t * 17 + j] - m);
            s_a[t * 17 + j] = p; s += p;
        }
        float inv = 1.f / s;
        for (int j = 0; j < 17; j++) s_a[t * 17 + j] *= inv;
    }
    __syncthreads();
    const int hd = t / (256 / HEADS);
    float acc = 0.f;
#pragma unroll
    for (int j = 0; j < 17; j++)
        acc = fmaf(s_a[hd * 17 + j], rec(hh, hl, (long)s_src[j] * 256 + t), acc);
    float o = acc + bias[t];
    if (do_relu) o = fmaxf(o, 0.f);
    if (oh) split1(o, oh, ol, (long)i * 256 + t);
    else    o32[(long)i * 256 + t] = o;
}

// ---------------- residual + LayerNorm, dual-plane ------------------------
__global__ void __launch_bounds__(256) add_ln_kernel(const bf16* __restrict__ xh,
                                                     const bf16* __restrict__ xl,
                                                     const bf16* __restrict__ th,
                                                     const bf16* __restrict__ tl,
                                                     const float* __restrict__ g,
                                                     const float* __restrict__ b,
                                                     bf16* __restrict__ oh,
                                                     bf16* __restrict__ ol)
{
    const int n = blockIdx.x, t = threadIdx.x;
    const long off = (long)n * 256 + t;
    float v = rec(xh, xl, off) + rec(th, tl, off);
    __shared__ float red[8];
    float s = v;
#pragma unroll
    for (int m = 16; m; m >>= 1) s += __shfl_xor_sync(0xffffffffu, s, m);
    if ((t & 31) == 0) red[t >> 5] = s;
    __syncthreads();
    float tot = 0.f;
#pragma unroll
    for (int w = 0; w < 8; w++) tot += red[w];
    float mu = tot * (1.f / 256.f);
    float d = v - mu;
    float sq = d * d;
#pragma unroll
    for (int m = 16; m; m >>= 1) sq += __shfl_xor_sync(0xffffffffu, sq, m);
    __syncthreads();
    if ((t & 31) == 0) red[t >> 5] = sq;
    __syncthreads();
    float tv = 0.f;
#pragma unroll
    for (int w = 0; w < 8; w++) tv += red[w];
    float var = tv * (1.f / 256.f);
    split1(d * rsqrtf(var + 1e-5f) * g[t] + b[t], oh, ol, off);
}

// ---------------- transpose [4096,256] fp32 -> [256,4096] -----------------
__global__ void transpose_kernel(const float* __restrict__ in, float* __restrict__ out)
{
    __shared__ float tile[32][33];
    const int bx = blockIdx.x * 32, by = blockIdx.y * 32;
    const int tx = threadIdx.x, ty = threadIdx.y;
#pragma unroll
    for (int p = 0; p < 4; p++)
        tile[ty + p * 8][tx] = in[(long)(by + ty + p * 8) * 256 + bx + tx];
    __syncthreads();
#pragma unroll
    for (int p = 0; p < 4; p++)
        out[(long)(bx + ty + p * 8) * 4096 + by + tx] = tile[tx][ty + p * 8];
}

// ---------------- launch ---------------------------------------------------
extern "C" void kernel_launch(void* const* d_in, const int* in_sizes, int n_in,
                              void* d_out, int out_size)
{
    const float* window   = (const float*)d_in[0];
    const float* gl_w     = (const float*)d_in[1];
    const float* gl_b     = (const float*)d_in[2];
    const float* enc_W    = (const float*)d_in[3];
    const float* enc_asrc = (const float*)d_in[4];
    const float* enc_adst = (const float*)d_in[5];
    const float* enc_b    = (const float*)d_in[6];
    const float* tr_wqkv  = (const float*)d_in[7];
    const float* tr_bqkv  = (const float*)d_in[8];
    const float* tr_wo    = (const float*)d_in[9];
    const float* tr_bo    = (const float*)d_in[10];
    const float* ln1g     = (const float*)d_in[11];
    const float* ln1b     = (const float*)d_in[12];
    const float* tr_w1    = (const float*)d_in[13];
    const float* tr_b1    = (const float*)d_in[14];
    const float* tr_w2    = (const float*)d_in[15];
    const float* tr_b2    = (const float*)d_in[16];
    const float* ln2g     = (const float*)d_in[17];
    const float* ln2b     = (const float*)d_in[18];
    const float* skip_w   = (const float*)d_in[19];
    const float* skip_b   = (const float*)d_in[20];
    const float* dec_W    = (const float*)d_in[21];
    const float* dec_asrc = (const float*)d_in[22];
    const float* dec_adst = (const float*)d_in[23];
    const float* dec_b    = (const float*)d_in[24];
    const float* dec_lW   = (const float*)d_in[25];
    const float* dec_lasrc= (const float*)d_in[26];
    const float* dec_ladst= (const float*)d_in[27];
    const float* dec_lb   = (const float*)d_in[28];

    bf16 *winh, *winl, *h0h, *h0l, *xh, *xl, *yh, *yl, *th, *tl;
    bf16 *qkvh, *qkvl, *ffh, *ffl, *simh, *siml, *wh, *wl;
    float *tb, *ssrc, *sdst;
    int* idxb;
    cudaGetSymbolAddress((void**)&winh, g_win_h); cudaGetSymbolAddress((void**)&winl, g_win_l);
    cudaGetSymbolAddress((void**)&h0h,  g_h0_h);  cudaGetSymbolAddress((void**)&h0l,  g_h0_l);
    cudaGetSymbolAddress((void**)&xh,   g_x_h);   cudaGetSymbolAddress((void**)&xl,   g_x_l);
    cudaGetSymbolAddress((void**)&yh,   g_y_h);   cudaGetSymbolAddress((void**)&yl,   g_y_l);
    cudaGetSymbolAddress((void**)&th,   g_t_h);   cudaGetSymbolAddress((void**)&tl,   g_t_l);
    cudaGetSymbolAddress((void**)&qkvh, g_qkv_h); cudaGetSymbolAddress((void**)&qkvl, g_qkv_l);
    cudaGetSymbolAddress((void**)&ffh,  g_ff_h);  cudaGetSymbolAddress((void**)&ffl,  g_ff_l);
    cudaGetSymbolAddress((void**)&simh, g_sim_h); cudaGetSymbolAddress((void**)&siml, g_sim_l);
    cudaGetSymbolAddress((void**)&wh,   g_w_h);   cudaGetSymbolAddress((void**)&wl,   g_w_l);
    cudaGetSymbolAddress((void**)&tb,   g_tb);
    cudaGetSymbolAddress((void**)&ssrc, g_ssrc);  cudaGetSymbolAddress((void**)&sdst, g_sdst);
    cudaGetSymbolAddress((void**)&idxb, g_idx);

    const long O_GLW = 0,       O_ENCW = 65536,  O_WQKV = 262144, O_WO = 655360;
    const long O_W1 = 786432,   O_W2 = 1048576,  O_SKIP = 1310720;
    const long O_DECW = 1376256, O_DECL = 1507328;

    dim3 blk(256), tblk(32, 8);

    // ---- conversions + early GEMMs, ordered so ncu (-s 5) captures sim GEMM
    conv_k<<<NN * DD / 256, blk>>>(window, winh, winl, NN * DD);             // 1
    convT_k<<<dim3(8, 8, 1), tblk>>>(gl_w, wh + O_GLW, wl + O_GLW, 256, 256);// 2
    gemm_bf3<64, 2><<<dim3(4, 32), blk>>>(winh, winl, DD,                    // 3: h0
        wh + O_GLW, wl + O_GLW, DD, gl_b, h0h, h0l, DD, DD, 0, 0, 0, 1.f);
    conv_k<<<1536, blk>>>(tr_wqkv, wh + O_WQKV, wl + O_WQKV, 393216);        // 4
    convT_k<<<dim3(8, 8, 3), tblk>>>(enc_W, wh + O_ENCW, wl + O_ENCW, 256, 256); // 5
    gemm_bf3<128, 0><<<dim3(32, 32), blk>>>(h0h, h0l, DD, h0h, h0l, DD,      // 6: sim (ncu)
        nullptr, simh, siml, NN, DD, 0, 0, 0, 1.f);
    topk_kernel<<<NN, blk>>>(simh, siml, idxb);                              // 7
    conv_k<<<512, blk>>>(tr_wo, wh + O_WO, wl + O_WO, 131072);               // 8
    convT_k<<<dim3(16, 8, 2), tblk>>>(tr_w1, wh + O_W1, wl + O_W1, 256, 512);// 9
    convT_k<<<dim3(8, 16, 2), tblk>>>(tr_w2, wh + O_W2, wl + O_W2, 512, 256);// 10
    convT_k<<<dim3(8, 8, 2), tblk>>>(dec_W, wh + O_DECW, wl + O_DECW, 256, 256); // 11
    convT_k<<<dim3(8, 8, 1), tblk>>>(skip_w, wh + O_SKIP, wl + O_SKIP, 256, 256);// 12
    convT_k<<<dim3(8, 8, 1), tblk>>>(dec_lW, wh + O_DECL, wl + O_DECL, 256, 256);// 13

    // ---- encoder: 3x GAT(4 heads) + relu
    const bf16* xih = winh; const bf16* xil = winl;
    for (int i = 0; i < 3; i++) {
        gemm_bf3<64, 0><<<dim3(4, 32), blk>>>(xih, xil, DD,
            wh + O_ENCW + i * 65536, wl + O_ENCW + i * 65536, DD,
            nullptr, yh, yl, DD, DD, 0, 0, 0, 1.f);
        gat_scores<<<NN, blk>>>(yh, yl, enc_asrc + i * 256, enc_adst + i * 256, ssrc, sdst, 4);
        gat_agg<4><<<NN, blk>>>(yh, yl, ssrc, sdst, idxb, enc_b + i * DD, xh, xl, nullptr, 1);
        xih = xh; xil = xl;
    }

    // ---- transformer bottleneck: 2 layers (fused flash attention)
    for (int i = 0; i < 2; i++) {
        // qkv = x @ wqkv^T + bqkv; Q cols pre-scaled by log2e/8 (ACT=4)
        gemm_bf3<128, 4><<<dim3(6, 32), blk>>>(xh, xl, DD,
            wh + O_WQKV + i * 196608, wl + O_WQKV + i * 196608, DD,
            tr_bqkv + i * 768, qkvh, qkvl, 768, DD, 0, 0, 0, 1.f);
        flash_attn<<<dim3(32, 4), blk>>>(qkvh, qkvl, yh, yl);
        gemm_bf3<64, 0><<<dim3(4, 32), blk>>>(yh, yl, DD,
            wh + O_WO + i * 65536, wl + O_WO + i * 65536, DD,
            tr_bo + i * DD, th, tl, DD, DD, 0, 0, 0, 1.f);
        add_ln_kernel<<<NN, blk>>>(xh, xl, th, tl, ln1g + i * DD, ln1b + i * DD, xh, xl);
        gemm_bf3<128, 1><<<dim3(4, 32), blk>>>(xh, xl, DD,
            wh + O_W1 + i * 131072, wl + O_W1 + i * 131072, DD,
            tr_b1 + i * 512, ffh, ffl, 512, DD, 0, 0, 0, 1.f);
        gemm_bf3<64, 0><<<dim3(4, 32), blk>>>(ffh, ffl, 512,
            wh + O_W2 + i * 131072, wl + O_W2 + i * 131072, 512,
            tr_b2 + i * DD, th, tl, DD, 512, 0, 0, 0, 1.f);
        add_ln_kernel<<<NN, blk>>>(xh, xl, th, tl, ln2g + i * DD, ln2b + i * DD, xh, xl);
    }

    // ---- skip connection fused into GEMM (ACT=3: C += window @ skip_w + b)
    gemm_bf3<64, 3><<<dim3(4, 32), blk>>>(winh, winl, DD, wh + O_SKIP, wl + O_SKIP, DD,
        skip_b, xh, xl, DD, DD, 0, 0, 0, 1.f);

    // ---- decoder: 2x GAT(4 heads)+relu, then single-head GAT
    for (int i = 0; i < 2; i++) {
        gemm_bf3<64, 0><<<dim3(4, 32), blk>>>(xh, xl, DD,
            wh + O_DECW + i * 65536, wl + O_DECW + i * 65536, DD,
            nullptr, yh, yl, DD, DD, 0, 0, 0, 1.f);
        gat_scores<<<NN, blk>>>(yh, yl, dec_asrc + i * 256, dec_adst + i * 256, ssrc, sdst, 4);
        gat_agg<4><<<NN, blk>>>(yh, yl, ssrc, sdst, idxb, dec_b + i * DD, xh, xl, nullptr, 1);
    }
    gemm_bf3<64, 0><<<dim3(4, 32), blk>>>(xh, xl, DD, wh + O_DECL, wl + O_DECL, DD,
        nullptr, yh, yl, DD, DD, 0, 0, 0, 1.f);
    gat_scores<<<NN, blk>>>(yh, yl, dec_lasrc, dec_ladst, ssrc, sdst, 1);
    gat_agg<1><<<NN, blk>>>(yh, yl, ssrc, sdst, idxb, dec_lb, nullptr, nullptr, tb, 0);

    // ---- output: transpose to [256, 4096]
    transpose_kernel<<<dim3(8, 128), dim3(32, 8)>>>(tb, (float*)d_out);
}

// round 15
// speedup vs baseline: 1.1474x; 1.1089x over previous
#include <cuda_runtime.h>
#include <cuda_bf16.h>
#include <math.h>
#include <stdint.h>

typedef __nv_bfloat16 bf16;

#define NN 4096
#define DD 256

// ---------------- scratch (device globals; no allocation) ----------------
__device__ bf16 g_win_h[NN * DD], g_win_l[NN * DD];
__device__ bf16 g_h0_h[NN * DD],  g_h0_l[NN * DD];
__device__ bf16 g_x_h[NN * DD],   g_x_l[NN * DD];
__device__ bf16 g_y_h[NN * DD],   g_y_l[NN * DD];
__device__ bf16 g_t_h[NN * DD],   g_t_l[NN * DD];
__device__ bf16 g_qkv_h[NN * 768], g_qkv_l[NN * 768];
__device__ bf16 g_ff_h[NN * 512],  g_ff_l[NN * 512];
__device__ bf16 g_sim_h[(long)NN * NN], g_sim_l[(long)NN * NN];   // 32MB each
#define WPOOL 1572864
__device__ bf16 g_w_h[WPOOL], g_w_l[WPOOL];
__device__ float g_op[2L * NN * DD];         // split-KV O partials (fp32)
__device__ float g_mv[8 * NN], g_lv[8 * NN]; // [z][h][row] m / l
__device__ float g_tb[NN * DD];
__device__ float g_ssrc[NN * 4], g_sdst[NN * 4];
__device__ int   g_idx[NN * 16];

// ---------------- helpers -------------------------------------------------
__device__ __forceinline__ void cp16(uint32_t dst, const void* src) {
    asm volatile("cp.async.cg.shared.global [%0], [%1], 16;" :: "r"(dst), "l"(src));
}
#define CP_COMMIT() asm volatile("cp.async.commit_group;")

__device__ __forceinline__ float rec(const bf16* H, const bf16* L, long i) {
    return __bfloat162float(H[i]) + __bfloat162float(L[i]);
}
__device__ __forceinline__ void split1(float v, bf16* H, bf16* L, long off) {
    bf16 h = __float2bfloat16(v);
    H[off] = h;
    L[off] = __float2bfloat16(v - __bfloat162float(h));
}
__device__ __forceinline__ uint32_t pk(bf16 a, bf16 b) {
    __nv_bfloat162 t = __halves2bfloat162(a, b);
    return *(uint32_t*)&t;
}
__device__ __forceinline__ uint32_t pkf(float lo_v, float hi_v) {
    uint32_t r;
    asm("cvt.rn.bf16x2.f32 %0, %1, %2;" : "=r"(r) : "f"(hi_v), "f"(lo_v));
    return r;
}
__device__ __forceinline__ void split2st(float v0, float v1, bf16* H, bf16* L, long off) {
    bf16 h0 = __float2bfloat16(v0), h1 = __float2bfloat16(v1);
    float r0 = v0 - __bfloat162float(h0), r1 = v1 - __bfloat162float(h1);
    *(uint32_t*)(H + off) = pk(h0, h1);
    *(uint32_t*)(L + off) = pk(__float2bfloat16(r0), __float2bfloat16(r1));
}
// Truncation split (P path only): hi = bitwise truncate (exact residual in fp32)
__device__ __forceinline__ void splitpk(float v0, float v1, uint32_t& hi, uint32_t& lo) {
    uint32_t u0 = __float_as_uint(v0) & 0xFFFF0000u;
    uint32_t u1 = __float_as_uint(v1) & 0xFFFF0000u;
    hi = (u0 >> 16) | u1;
    lo = pkf(v0 - __uint_as_float(u0), v1 - __uint_as_float(u1));
}
__device__ __forceinline__ float ex2(float x) {
    float r; asm("ex2.approx.f32 %0, %1;" : "=f"(r) : "f"(x)); return r;
}

#define MMA_BF16(c, a, b0, b1) \
    asm volatile("mma.sync.aligned.m16n8k16.row.col.f32.bf16.bf16.f32 " \
                 "{%0,%1,%2,%3},{%4,%5,%6,%7},{%8,%9},{%0,%1,%2,%3};" \
                 : "+f"((c)[0]), "+f"((c)[1]), "+f"((c)[2]), "+f"((c)[3]) \
                 : "r"((a)[0]), "r"((a)[1]), "r"((a)[2]), "r"((a)[3]), \
                   "r"(b0), "r"(b1))

#define LDSM4(r, addr) \
    asm volatile("ldmatrix.sync.aligned.m8n8.x4.shared.b16 {%0,%1,%2,%3}, [%4];" \
                 : "=r"((r)[0]), "=r"((r)[1]), "=r"((r)[2]), "=r"((r)[3]) \
                 : "r"(addr))

#define LDSM4T(r, addr) \
    asm volatile("ldmatrix.sync.aligned.m8n8.x4.trans.shared.b16 {%0,%1,%2,%3}, [%4];" \
                 : "=r"((r)[0]), "=r"((r)[1]), "=r"((r)[2]), "=r"((r)[3]) \
                 : "r"(addr))

// ---------------- split-bf16 3-product GEMM (both operands k-major) -------
// ACT: 0 none, 1 relu, 2 tanh, 3 accumulate-into-C, 4 qkv (scale cols<256 by
// log2e/8), 5 = none + fused GAT scores (BN=64, head = bn/64, bias=null).
template<int BN, int ACT>
__global__ void __launch_bounds__(256) gemm_bf3(
    const bf16* __restrict__ Ah, const bf16* __restrict__ Al, int lda,
    const bf16* __restrict__ Bh, const bf16* __restrict__ Bl, int ldb,
    const float* __restrict__ bias,
    bf16* __restrict__ Ch, bf16* __restrict__ Cl, int ldc,
    int K, long sAz, long sBz, long sCz, float alpha,
    const float* __restrict__ asrc, const float* __restrict__ adst,
    float* __restrict__ ssrc, float* __restrict__ sdst)
{
    constexpr int NI = BN / 32;
    __shared__ bf16 sAh[2][128 * 24], sAl[2][128 * 24];
    __shared__ bf16 sBh[2][BN * 24],  sBl[2][BN * 24];

    const int tid = threadIdx.x;
    const int warp = tid >> 5, lane = tid & 31;
    const int g = lane >> 2, tig = lane & 3;
    const int wm = warp & 1, wn = warp >> 1;
    const int wm0 = wm * 64, wn0 = wn * (BN / 4);
    const int bm = blockIdx.y * 128, bn = blockIdx.x * BN;
    const long z = blockIdx.z;
    Ah += z * sAz; Al += z * sAz;
    Bh += z * sBz; Bl += z * sBz;
    Ch += z * sCz; Cl += z * sCz;

    const uint32_t offA = (uint32_t)(((wm0 + (lane & 15)) * 24 + (lane >> 4) * 8) * 2);
    const uint32_t offB = (uint32_t)(((wn0 + ((lane >> 4) & 1) * 8 + (lane & 7)) * 24
                                      + ((lane >> 3) & 1) * 8) * 2);
    uint32_t bAh[2] = { (uint32_t)__cvta_generic_to_shared(&sAh[0][0]),
                        (uint32_t)__cvta_generic_to_shared(&sAh[1][0]) };
    uint32_t bAl[2] = { (uint32_t)__cvta_generic_to_shared(&sAl[0][0]),
                        (uint32_t)__cvta_generic_to_shared(&sAl[1][0]) };
    uint32_t bBh[2] = { (uint32_t)__cvta_generic_to_shared(&sBh[0][0]),
                        (uint32_t)__cvta_generic_to_shared(&sBh[1][0]) };
    uint32_t bBl[2] = { (uint32_t)__cvta_generic_to_shared(&sBl[0][0]),
                        (uint32_t)__cvta_generic_to_shared(&sBl[1][0]) };

    float acc[4][NI][4];
#pragma unroll
    for (int mi = 0; mi < 4; mi++)
#pragma unroll
        for (int ni = 0; ni < NI; ni++)
#pragma unroll
            for (int q = 0; q < 4; q++) acc[mi][ni][q] = 0.f;

    auto load_tile = [&](int t, int buf) {
        const int k0 = t * 16;
        {
            int row = tid >> 1, half = tid & 1;
            uint32_t off = (uint32_t)(row * 24 + half * 8) * 2;
            long src = (long)(bm + row) * lda + k0 + half * 8;
            cp16(bAh[buf] + off, Ah + src);
            cp16(bAl[buf] + off, Al + src);
        }
        if (BN == 128 || tid < BN * 2) {
            int row = tid >> 1, half = tid & 1;
            uint32_t off = (uint32_t)(row * 24 + half * 8) * 2;
            long src = (long)(bn + row) * ldb + k0 + half * 8;
            cp16(bBh[buf] + off, Bh + src);
            cp16(bBl[buf] + off, Bl + src);
        }
    };

    load_tile(0, 0);
    CP_COMMIT();
    const int nt = K / 16;

    for (int t = 0; t < nt; t++) {
        if (t + 1 < nt) {
            load_tile(t + 1, (t + 1) & 1);
            CP_COMMIT();
            asm volatile("cp.async.wait_group 1;");
        } else {
            asm volatile("cp.async.wait_group 0;");
        }
        __syncthreads();
        const int buf = t & 1;

        uint32_t fah[4][4], fal[4][4];
#pragma unroll
        for (int mi = 0; mi < 4; mi++) {
            LDSM4(fah[mi], bAh[buf] + offA + mi * 768);
            LDSM4(fal[mi], bAl[buf] + offA + mi * 768);
        }
        uint32_t bh[NI][2], bl[NI][2];
#pragma unroll
        for (int pi = 0; pi < NI / 2; pi++) {
            LDSM4(bh[2 * pi], bBh[buf] + offB + pi * 768);
            LDSM4(bl[2 * pi], bBl[buf] + offB + pi * 768);
        }
#pragma unroll
        for (int ni = 0; ni < NI; ni++) {
#pragma unroll
            for (int mi = 0; mi < 4; mi++) {
                MMA_BF16(acc[mi][ni], fah[mi], bh[ni][0], bh[ni][1]);
                MMA_BF16(acc[mi][ni], fal[mi], bh[ni][0], bh[ni][1]);
                MMA_BF16(acc[mi][ni], fah[mi], bl[ni][0], bl[ni][1]);
            }
        }
        __syncthreads();
    }

    // ---- epilogue (sA dead; ACT==5 reuses it for score reduction) ----
    float* sS = (float*)&sAh[0][0];
    float* sD = sS + 128;
    if (ACT == 5) {
        if (tid < 128) { sS[tid] = 0.f; sD[tid] = 0.f; }
        __syncthreads();
    }
    float ps[4][2], pd[4][2];
    if (ACT == 5) {
#pragma unroll
        for (int mi = 0; mi < 4; mi++)
#pragma unroll
            for (int h2 = 0; h2 < 2; h2++) { ps[mi][h2] = 0.f; pd[mi][h2] = 0.f; }
    }
#pragma unroll
    for (int mi = 0; mi < 4; mi++) {
#pragma unroll
        for (int ni = 0; ni < NI; ni++) {
            int col = bn + wn0 + ni * 8 + tig * 2;
            float b0 = 0.f, b1 = 0.f;
            if (bias) { b0 = bias[col]; b1 = bias[col + 1]; }
            float a0, a1, d0, d1;
            if (ACT == 5) { a0 = asrc[col]; a1 = asrc[col + 1];
                            d0 = adst[col]; d1 = adst[col + 1]; }
#pragma unroll
            for (int h2 = 0; h2 < 2; h2++) {
                int row = bm + wm0 + mi * 16 + g + h2 * 8;
                long off = (long)row * ldc + col;
                float v0 = acc[mi][ni][h2 * 2 + 0] * alpha + b0;
                float v1 = acc[mi][ni][h2 * 2 + 1] * alpha + b1;
                if (ACT == 1) { v0 = fmaxf(v0, 0.f); v1 = fmaxf(v1, 0.f); }
                if (ACT == 2) { v0 = tanhf(v0); v1 = tanhf(v1); }
                if (ACT == 3) { v0 += rec(Ch, Cl, off); v1 += rec(Ch, Cl, off + 1); }
                if (ACT == 4 && col < 256) { v0 *= 0.18033688011112042f; v1 *= 0.18033688011112042f; }
                if (ACT == 5) {
                    ps[mi][h2] += v0 * a0 + v1 * a1;
                    pd[mi][h2] += v0 * d0 + v1 * d1;
                }
                split2st(v0, v1, Ch, Cl, off);
            }
        }
    }
    if (ACT == 5) {
#pragma unroll
        for (int mi = 0; mi < 4; mi++)
#pragma unroll
            for (int h2 = 0; h2 < 2; h2++) {
                float a = ps[mi][h2], d = pd[mi][h2];
                a += __shfl_xor_sync(0xffffffffu, a, 1);
                a += __shfl_xor_sync(0xffffffffu, a, 2);
                d += __shfl_xor_sync(0xffffffffu, d, 1);
                d += __shfl_xor_sync(0xffffffffu, d, 2);
                if (tig == 0) {
                    atomicAdd(&sS[wm0 + mi * 16 + g + h2 * 8], a);
                    atomicAdd(&sD[wm0 + mi * 16 + g + h2 * 8], d);
                }
            }
        __syncthreads();
        if (tid < 128) {
            ssrc[(long)(bm + tid) * 4 + (bn >> 6)] = sS[tid];
            sdst[(long)(bm + tid) * 4 + (bn >> 6)] = sD[tid];
        }
    }
}

// ---------------- fused flash attention, split-KV (bf3, dual-plane P) -----
// grid (32, 4, 2): 128 q-rows, head = y, KV half = z (2048 keys each).
// Emits unnormalized fp32 O partial + per-row (m, l); attn_merge combines.
__global__ void __launch_bounds__(256, 2) flash_attn(
    const bf16* __restrict__ Qh, const bf16* __restrict__ Ql,
    float* __restrict__ op, float* __restrict__ mv, float* __restrict__ lv)
{
    __shared__ char smem[2 * 18432];   // Q staging, then KV double buffer
    const int tid = threadIdx.x, lane = tid & 31, w = tid >> 5;
    const int g = lane >> 2, tig = lane & 3;
    const int q0 = blockIdx.x * 128;
    const int h = blockIdx.y;
    const int z = blockIdx.z;
    const uint32_t sbase = (uint32_t)__cvta_generic_to_shared(smem);

    // ---- stage Q tile (128x64, dual plane, stride 72 elems = 144B)
#pragma unroll
    for (int c = tid; c < 1024; c += 256) {
        int row = c >> 3, off = (c & 7) * 8;
        long src = (long)(q0 + row) * 768 + h * 64 + off;
        cp16(sbase + row * 144 + off * 2, Qh + src);
        cp16(sbase + 18432 + row * 144 + off * 2, Ql + src);
    }
    CP_COMMIT();
    asm volatile("cp.async.wait_group 0;");
    __syncthreads();

    uint32_t fqh[4][4], fql[4][4];
    {
        uint32_t offQ = (uint32_t)(((w * 16 + (lane & 15)) * 72 + (lane >> 4) * 8) * 2);
#pragma unroll
        for (int j = 0; j < 4; j++) {
            LDSM4(fqh[j], sbase + offQ + j * 32);
            LDSM4(fql[j], sbase + 18432 + offQ + j * 32);
        }
    }
    __syncthreads();   // Q reads done; smem reused as K/V buffers

    // KV buffer layout per stage (18432B): kh 0 / kl 4608 / vh 9216 / vl 13824
    auto load_kv = [&](int t, int b) {
        uint32_t base = sbase + b * 18432;
        int row = tid >> 3, off = (tid & 7) * 8;
        long key = (long)t * 32 + row;
        long srcK = key * 768 + 256 + h * 64 + off;
        long srcV = key * 768 + 512 + h * 64 + off;
        uint32_t d = row * 144 + off * 2;
        cp16(base + d,         Qh + srcK);
        cp16(base + 4608 + d,  Ql + srcK);
        cp16(base + 9216 + d,  Qh + srcV);
        cp16(base + 13824 + d, Ql + srcV);
    };

    const uint32_t offK = (uint32_t)(((((lane >> 4) & 1) * 8 + (lane & 7)) * 72
                                      + ((lane >> 3) & 1) * 8) * 2);
    const uint32_t offV = (uint32_t)(((lane & 15) * 72 + (lane >> 4) * 8) * 2);

    float m0v = -1e30f, m1v = -1e30f, l0 = 0.f, l1 = 0.f;
    float o[8][4];
#pragma unroll
    for (int nd = 0; nd < 8; nd++)
#pragma unroll
        for (int q = 0; q < 4; q++) o[nd][q] = 0.f;

    const int t0 = z * 64, t1 = t0 + 64;
    load_kv(t0, t0 & 1);
    CP_COMMIT();

    for (int t = t0; t < t1; t++) {
        if (t + 1 < t1) {
            load_kv(t + 1, (t + 1) & 1);
            CP_COMMIT();
            asm volatile("cp.async.wait_group 1;");
        } else {
            asm volatile("cp.async.wait_group 0;");
        }
        __syncthreads();
        const uint32_t kb = sbase + (t & 1) * 18432;

        // ---- S = Q @ K^T (log2-domain, Q pre-scaled) : 16 rows x 32 keys/warp
        float s[4][4];
#pragma unroll
        for (int ni = 0; ni < 4; ni++)
#pragma unroll
            for (int q = 0; q < 4; q++) s[ni][q] = 0.f;
#pragma unroll
        for (int j = 0; j < 4; j++) {
            uint32_t bh[4], bl[4];
            LDSM4(bh, kb + offK + j * 32);                 // keys 0-15
            LDSM4(bl, kb + 4608 + offK + j * 32);
            MMA_BF16(s[0], fqh[j], bh[0], bh[1]);
            MMA_BF16(s[0], fql[j], bh[0], bh[1]);
            MMA_BF16(s[0], fqh[j], bl[0], bl[1]);
            MMA_BF16(s[1], fqh[j], bh[2], bh[3]);
            MMA_BF16(s[1], fql[j], bh[2], bh[3]);
            MMA_BF16(s[1], fqh[j], bl[2], bl[3]);
            uint32_t ch[4], cl[4];
            LDSM4(ch, kb + offK + 2304 + j * 32);          // keys 16-31
            LDSM4(cl, kb + 4608 + offK + 2304 + j * 32);
            MMA_BF16(s[2], fqh[j], ch[0], ch[1]);
            MMA_BF16(s[2], fql[j], ch[0], ch[1]);
            MMA_BF16(s[2], fqh[j], cl[0], cl[1]);
            MMA_BF16(s[3], fqh[j], ch[2], ch[3]);
            MMA_BF16(s[3], fql[j], ch[2], ch[3]);
            MMA_BF16(s[3], fqh[j], cl[2], cl[3]);
        }

        // ---- online softmax, base 2 (rows g and g+8; row spread over 4 lanes)
        float ml0 = -1e30f, ml1 = -1e30f;
#pragma unroll
        for (int ni = 0; ni < 4; ni++) {
            ml0 = fmaxf(ml0, fmaxf(s[ni][0], s[ni][1]));
            ml1 = fmaxf(ml1, fmaxf(s[ni][2], s[ni][3]));
        }
        ml0 = fmaxf(ml0, __shfl_xor_sync(0xffffffffu, ml0, 1));
        ml0 = fmaxf(ml0, __shfl_xor_sync(0xffffffffu, ml0, 2));
        ml1 = fmaxf(ml1, __shfl_xor_sync(0xffffffffu, ml1, 1));
        ml1 = fmaxf(ml1, __shfl_xor_sync(0xffffffffu, ml1, 2));
        float mn0 = fmaxf(m0v, ml0), mn1 = fmaxf(m1v, ml1);
        float c0 = ex2(m0v - mn0), c1 = ex2(m1v - mn1);
        m0v = mn0; m1v = mn1;
        float rs0 = 0.f, rs1 = 0.f;
#pragma unroll
        for (int ni = 0; ni < 4; ni++) {
            s[ni][0] = ex2(s[ni][0] - mn0); rs0 += s[ni][0];
            s[ni][1] = ex2(s[ni][1] - mn0); rs0 += s[ni][1];
            s[ni][2] = ex2(s[ni][2] - mn1); rs1 += s[ni][2];
            s[ni][3] = ex2(s[ni][3] - mn1); rs1 += s[ni][3];
        }
        rs0 += __shfl_xor_sync(0xffffffffu, rs0, 1);
        rs0 += __shfl_xor_sync(0xffffffffu, rs0, 2);
        rs1 += __shfl_xor_sync(0xffffffffu, rs1, 1);
        rs1 += __shfl_xor_sync(0xffffffffu, rs1, 2);
        l0 = l0 * c0 + rs0;
        l1 = l1 * c1 + rs1;
        if (__any_sync(0xffffffffu, (c0 != 1.f) || (c1 != 1.f))) {
#pragma unroll
            for (int nd = 0; nd < 8; nd++) {
                o[nd][0] *= c0; o[nd][1] *= c0;
                o[nd][2] *= c1; o[nd][3] *= c1;
            }
        }

        // ---- O += P @ V  (P truncation-split in registers, V via ldmatrix.trans)
#pragma unroll
        for (int c = 0; c < 2; c++) {
            uint32_t ah[4], al[4];
            splitpk(s[2 * c][0],     s[2 * c][1],     ah[0], al[0]);
            splitpk(s[2 * c][2],     s[2 * c][3],     ah[1], al[1]);
            splitpk(s[2 * c + 1][0], s[2 * c + 1][1], ah[2], al[2]);
            splitpk(s[2 * c + 1][2], s[2 * c + 1][3], ah[3], al[3]);
#pragma unroll
            for (int gg = 0; gg < 4; gg++) {
                uint32_t vh4[4], vl4[4];
                LDSM4T(vh4, kb + 9216 + offV + c * 2304 + gg * 32);
                LDSM4T(vl4, kb + 13824 + offV + c * 2304 + gg * 32);
                MMA_BF16(o[2 * gg],     ah, vh4[0], vh4[1]);
                MMA_BF16(o[2 * gg],     al, vh4[0], vh4[1]);
                MMA_BF16(o[2 * gg],     ah, vl4[0], vl4[1]);
                MMA_BF16(o[2 * gg + 1], ah, vh4[2], vh4[3]);
                MMA_BF16(o[2 * gg + 1], al, vh4[2], vh4[3]);
                MMA_BF16(o[2 * gg + 1], ah, vl4[2], vl4[3]);
            }
        }
        __syncthreads();
    }

    // ---- store unnormalized partial + (m, l)
    const long zo = (long)z * NN * DD;
    const int r0 = q0 + w * 16 + g, r1 = r0 + 8;
    if (tig == 0) {
        float* mz = mv + (long)z * 4 * NN + (long)h * NN;
        float* lz = lv + (long)z * 4 * NN + (long)h * NN;
        mz[r0] = m0v; mz[r1] = m1v;
        lz[r0] = l0;  lz[r1] = l1;
    }
#pragma unroll
    for (int nd = 0; nd < 8; nd++) {
        int col = h * 64 + nd * 8 + tig * 2;
        *(float2*)&op[zo + (long)r0 * 256 + col] = make_float2(o[nd][0], o[nd][1]);
        *(float2*)&op[zo + (long)r1 * 256 + col] = make_float2(o[nd][2], o[nd][3]);
    }
}

// ---------------- split-KV merge ------------------------------------------
__global__ void __launch_bounds__(256) attn_merge(
    const float* __restrict__ op, const float* __restrict__ mv,
    const float* __restrict__ lv, bf16* __restrict__ oh, bf16* __restrict__ ol)
{
    const int row = blockIdx.x, tid = threadIdx.x, h = tid >> 6;
    const long i = (long)row * 256 + tid;
    const long hi = (long)h * NN + row;
    float m0 = mv[hi], m1 = mv[4 * NN + hi];
    float l0 = lv[hi], l1 = lv[4 * NN + hi];
    float M = fmaxf(m0, m1);
    float c0 = ex2(m0 - M), c1 = ex2(m1 - M);
    float L = l0 * c0 + l1 * c1;
    float v = (op[i] * c0 + op[(long)NN * DD + i] * c1) / L;
    split1(v, oh, ol, i);
}

// ---------------- conversions (z-batched via blockIdx.z) ------------------
__global__ void conv_k(const float* __restrict__ in, bf16* __restrict__ oh,
                       bf16* __restrict__ ol, int n)
{
    int i = blockIdx.x * 256 + threadIdx.x;
    if (i < n) split1(in[i], oh, ol, i);
}

__global__ void convT_k(const float* __restrict__ in, bf16* __restrict__ oh,
                        bf16* __restrict__ ol, int K, int N)
{
    __shared__ float tile[32][33];
    const long zoff = (long)blockIdx.z * K * N;
    in += zoff; oh += zoff; ol += zoff;
    const int k0 = blockIdx.y * 32, n0 = blockIdx.x * 32;
    const int tx = threadIdx.x, ty = threadIdx.y;
#pragma unroll
    for (int p = 0; p < 4; p++)
        tile[ty + p * 8][tx] = in[(long)(k0 + ty + p * 8) * N + n0 + tx];
    __syncthreads();
#pragma unroll
    for (int p = 0; p < 4; p++) {
        int n = n0 + ty + p * 8, k = k0 + tx;
        split1(tile[tx][ty + p * 8], oh, ol, (long)n * K + k);
    }
}

// ---------------- top-16 per row (packed u64 warp-shuffle reduction) ------
__global__ void __launch_bounds__(256) topk_kernel(const bf16* __restrict__ Sh,
                                                   const bf16* __restrict__ Sl,
                                                   int* __restrict__ idx)
{
    const int row = blockIdx.x, t = threadIdx.x;
    const int lane = t & 31, warp = t >> 5;
    unsigned long long lv[16];
#pragma unroll
    for (int i = 0; i < 16; i++) {
        int j = i * 256 + t;
        float v = fmaxf(rec(Sh, Sl, (long)row * NN + j), 0.f);
        unsigned long long p =
            ((unsigned long long)__float_as_uint(v) << 32) | (unsigned)(~j);
        if (j == row) p = 0ull;
        lv[i] = p;
    }
    __shared__ unsigned long long sw[8];
    for (int r = 0; r < 16; r++) {
        unsigned long long best = lv[0];
#pragma unroll
        for (int i = 1; i < 16; i++) best = best > lv[i] ? best : lv[i];
#pragma unroll
        for (int m = 16; m; m >>= 1) {
            unsigned long long o = __shfl_xor_sync(0xffffffffu, best, m);
            best = best > o ? best : o;
        }
        if (lane == 0) sw[warp] = best;
        __syncthreads();
        unsigned long long w0 = sw[0];
#pragma unroll
        for (int q = 1; q < 8; q++) w0 = w0 > sw[q] ? w0 : sw[q];
        int winj = (int)(~(unsigned)(w0 & 0xFFFFFFFFull));
        if (t == 0) idx[row * 16 + r] = winj;
        if ((winj & 255) == t) lv[winj >> 8] = 0ull;
        __syncthreads();
    }
}

// ---------------- GAT score precompute (single-head final layer only) -----
__global__ void __launch_bounds__(256) gat_scores(const bf16* __restrict__ hh,
                                                  const bf16* __restrict__ hl,
                                                  const float* __restrict__ a_s,
                                                  const float* __restrict__ a_d,
                                                  float* __restrict__ ssrc,
                                                  float* __restrict__ sdst,
                                                  int heads)
{
    const int n = blockIdx.x, t = threadIdx.x;
    float hv = rec(hh, hl, (long)n * 256 + t);
    float ps = hv * a_s[t];
    float pd = hv * a_d[t];
#pragma unroll
    for (int m = 16; m; m >>= 1) {
        ps += __shfl_xor_sync(0xffffffffu, ps, m);
        pd += __shfl_xor_sync(0xffffffffu, pd, m);
    }
    __shared__ float ws[8], wd[8];
    if ((t & 31) == 0) { ws[t >> 5] = ps; wd[t >> 5] = pd; }
    __syncthreads();
    if (t < heads) {
        int wph = 8 / heads;
        float s = 0.f, d = 0.f;
        for (int w = 0; w < wph; w++) { s += ws[t * wph + w]; d += wd[t * wph + w]; }
        ssrc[n * heads + t] = s;
        sdst[n * heads + t] = d;
    }
}

// ---------------- GAT aggregation (17 in-edges per dst) -------------------
template<int HEADS>
__global__ void __launch_bounds__(256) gat_agg(const bf16* __restrict__ hh,
                                               const bf16* __restrict__ hl,
                                               const float* __restrict__ ssrc,
                                               const float* __restrict__ sdst,
                                               const int* __restrict__ idx,
                                               const float* __restrict__ bias,
                                               bf16* __restrict__ oh,
                                               bf16* __restrict__ ol,
                                               float* __restrict__ o32,
                                               int do_relu)
{
    const int i = blockIdx.x, t = threadIdx.x;
    __shared__ int   s_src[17];
    __shared__ float s_e[HEADS * 17];
    __shared__ float s_a[HEADS * 17];
    if (t < 16) s_src[t] = idx[i * 16 + t];
    if (t == 16) s_src[16] = i;
    __syncthreads();
    if (t < HEADS * 17) {
        int hh2 = t / 17, j = t % 17;
        float e = ssrc[s_src[j] * HEADS + hh2] + sdst[i * HEADS + hh2];
        s_e[t] = e > 0.f ? e : 0.2f * e;
    }
    __syncthreads();
    if (t < HEADS) {
        float m = -1e30f;
        for (int j = 0; j < 17; j++) m = fmaxf(m, s_e[t * 17 + j]);
        float s = 0.f;
        for (int j = 0; j < 17; j++) {
            float p = __expf(s_e[t * 17 + j] - m);
            s_a[t * 17 + j] = p; s += p;
        }
        float inv = 1.f / s;
        for (int j = 0; j < 17; j++) s_a[t * 17 + j] *= inv;
    }
    __syncthreads();
    const int hd = t / (256 / HEADS);
    float acc = 0.f;
#pragma unroll
    for (int j = 0; j < 17; j++)
        acc = fmaf(s_a[hd * 17 + j], rec(hh, hl, (long)s_src[j] * 256 + t), acc);
    float o = acc + bias[t];
    if (do_relu) o = fmaxf(o, 0.f);
    if (oh) split1(o, oh, ol, (long)i * 256 + t);
    else    o32[(long)i * 256 + t] = o;
}

// ---------------- residual + LayerNorm, dual-plane ------------------------
__global__ void __launch_bounds__(256) add_ln_kernel(const bf16* __restrict__ xh,
                                                     const bf16* __restrict__ xl,
                                                     const bf16* __restrict__ th,
                                                     const bf16* __restrict__ tl,
                                                     const float* __restrict__ g,
                                                     const float* __restrict__ b,
                                                     bf16* __restrict__ oh,
                                                     bf16* __restrict__ ol)
{
    const int n = blockIdx.x, t = threadIdx.x;
    const long off = (long)n * 256 + t;
    float v = rec(xh, xl, off) + rec(th, tl, off);
    __shared__ float red[8];
    float s = v;
#pragma unroll
    for (int m = 16; m; m >>= 1) s += __shfl_xor_sync(0xffffffffu, s, m);
    if ((t & 31) == 0) red[t >> 5] = s;
    __syncthreads();
    float tot = 0.f;
#pragma unroll
    for (int w = 0; w < 8; w++) tot += red[w];
    float mu = tot * (1.f / 256.f);
    float d = v - mu;
    float sq = d * d;
#pragma unroll
    for (int m = 16; m; m >>= 1) sq += __shfl_xor_sync(0xffffffffu, sq, m);
    __syncthreads();
    if ((t & 31) == 0) red[t >> 5] = sq;
    __syncthreads();
    float tv = 0.f;
#pragma unroll
    for (int w = 0; w < 8; w++) tv += red[w];
    float var = tv * (1.f / 256.f);
    split1(d * rsqrtf(var + 1e-5f) * g[t] + b[t], oh, ol, off);
}

// ---------------- transpose [4096,256] fp32 -> [256,4096] -----------------
__global__ void transpose_kernel(const float* __restrict__ in, float* __restrict__ out)
{
    __shared__ float tile[32][33];
    const int bx = blockIdx.x * 32, by = blockIdx.y * 32;
    const int tx = threadIdx.x, ty = threadIdx.y;
#pragma unroll
    for (int p = 0; p < 4; p++)
        tile[ty + p * 8][tx] = in[(long)(by + ty + p * 8) * 256 + bx + tx];
    __syncthreads();
#pragma unroll
    for (int p = 0; p < 4; p++)
        out[(long)(bx + ty + p * 8) * 4096 + by + tx] = tile[tx][ty + p * 8];
}

// ---------------- launch ---------------------------------------------------
extern "C" void kernel_launch(void* const* d_in, const int* in_sizes, int n_in,
                              void* d_out, int out_size)
{
    const float* window   = (const float*)d_in[0];
    const float* gl_w     = (const float*)d_in[1];
    const float* gl_b     = (const float*)d_in[2];
    const float* enc_W    = (const float*)d_in[3];
    const float* enc_asrc = (const float*)d_in[4];
    const float* enc_adst = (const float*)d_in[5];
    const float* enc_b    = (const float*)d_in[6];
    const float* tr_wqkv  = (const float*)d_in[7];
    const float* tr_bqkv  = (const float*)d_in[8];
    const float* tr_wo    = (const float*)d_in[9];
    const float* tr_bo    = (const float*)d_in[10];
    const float* ln1g     = (const float*)d_in[11];
    const float* ln1b     = (const float*)d_in[12];
    const float* tr_w1    = (const float*)d_in[13];
    const float* tr_b1    = (const float*)d_in[14];
    const float* tr_w2    = (const float*)d_in[15];
    const float* tr_b2    = (const float*)d_in[16];
    const float* ln2g     = (const float*)d_in[17];
    const float* ln2b     = (const float*)d_in[18];
    const float* skip_w   = (const float*)d_in[19];
    const float* skip_b   = (const float*)d_in[20];
    const float* dec_W    = (const float*)d_in[21];
    const float* dec_asrc = (const float*)d_in[22];
    const float* dec_adst = (const float*)d_in[23];
    const float* dec_b    = (const float*)d_in[24];
    const float* dec_lW   = (const float*)d_in[25];
    const float* dec_lasrc= (const float*)d_in[26];
    const float* dec_ladst= (const float*)d_in[27];
    const float* dec_lb   = (const float*)d_in[28];

    bf16 *winh, *winl, *h0h, *h0l, *xh, *xl, *yh, *yl, *th, *tl;
    bf16 *qkvh, *qkvl, *ffh, *ffl, *simh, *siml, *wh, *wl;
    float *tb, *ssrc, *sdst, *opb, *mvb, *lvb;
    int* idxb;
    cudaGetSymbolAddress((void**)&winh, g_win_h); cudaGetSymbolAddress((void**)&winl, g_win_l);
    cudaGetSymbolAddress((void**)&h0h,  g_h0_h);  cudaGetSymbolAddress((void**)&h0l,  g_h0_l);
    cudaGetSymbolAddress((void**)&xh,   g_x_h);   cudaGetSymbolAddress((void**)&xl,   g_x_l);
    cudaGetSymbolAddress((void**)&yh,   g_y_h);   cudaGetSymbolAddress((void**)&yl,   g_y_l);
    cudaGetSymbolAddress((void**)&th,   g_t_h);   cudaGetSymbolAddress((void**)&tl,   g_t_l);
    cudaGetSymbolAddress((void**)&qkvh, g_qkv_h); cudaGetSymbolAddress((void**)&qkvl, g_qkv_l);
    cudaGetSymbolAddress((void**)&ffh,  g_ff_h);  cudaGetSymbolAddress((void**)&ffl,  g_ff_l);
    cudaGetSymbolAddress((void**)&simh, g_sim_h); cudaGetSymbolAddress((void**)&siml, g_sim_l);
    cudaGetSymbolAddress((void**)&wh,   g_w_h);   cudaGetSymbolAddress((void**)&wl,   g_w_l);
    cudaGetSymbolAddress((void**)&opb,  g_op);
    cudaGetSymbolAddress((void**)&mvb,  g_mv);    cudaGetSymbolAddress((void**)&lvb,  g_lv);
    cudaGetSymbolAddress((void**)&tb,   g_tb);
    cudaGetSymbolAddress((void**)&ssrc, g_ssrc);  cudaGetSymbolAddress((void**)&sdst, g_sdst);
    cudaGetSymbolAddress((void**)&idxb, g_idx);

    const long O_GLW = 0,       O_ENCW = 65536,  O_WQKV = 262144, O_WO = 655360;
    const long O_W1 = 786432,   O_W2 = 1048576,  O_SKIP = 1310720;
    const long O_DECW = 1376256, O_DECL = 1507328;

    dim3 blk(256), tblk(32, 8);

    // ---- conversions + early GEMMs
    conv_k<<<NN * DD / 256, blk>>>(window, winh, winl, NN * DD);
    convT_k<<<dim3(8, 8, 1), tblk>>>(gl_w, wh + O_GLW, wl + O_GLW, 256, 256);
    gemm_bf3<64, 2><<<dim3(4, 32), blk>>>(winh, winl, DD,
        wh + O_GLW, wl + O_GLW, DD, gl_b, h0h, h0l, DD, DD, 0, 0, 0, 1.f,
        nullptr, nullptr, nullptr, nullptr);
    conv_k<<<1536, blk>>>(tr_wqkv, wh + O_WQKV, wl + O_WQKV, 393216);
    convT_k<<<dim3(8, 8, 3), tblk>>>(enc_W, wh + O_ENCW, wl + O_ENCW, 256, 256);
    gemm_bf3<128, 0><<<dim3(32, 32), blk>>>(h0h, h0l, DD, h0h, h0l, DD,
        nullptr, simh, siml, NN, DD, 0, 0, 0, 1.f,
        nullptr, nullptr, nullptr, nullptr);
    topk_kernel<<<NN, blk>>>(simh, siml, idxb);
    conv_k<<<512, blk>>>(tr_wo, wh + O_WO, wl + O_WO, 131072);
    convT_k<<<dim3(16, 8, 2), tblk>>>(tr_w1, wh + O_W1, wl + O_W1, 256, 512);
    convT_k<<<dim3(8, 16, 2), tblk>>>(tr_w2, wh + O_W2, wl + O_W2, 512, 256);
    convT_k<<<dim3(8, 8, 2), tblk>>>(dec_W, wh + O_DECW, wl + O_DECW, 256, 256);
    convT_k<<<dim3(8, 8, 1), tblk>>>(skip_w, wh + O_SKIP, wl + O_SKIP, 256, 256);
    convT_k<<<dim3(8, 8, 1), tblk>>>(dec_lW, wh + O_DECL, wl + O_DECL, 256, 256);

    // ---- encoder: 3x GAT(4 heads) + relu (scores fused in GEMM, ACT=5)
    const bf16* xih = winh; const bf16* xil = winl;
    for (int i = 0; i < 3; i++) {
        gemm_bf3<64, 5><<<dim3(4, 32), blk>>>(xih, xil, DD,
            wh + O_ENCW + i * 65536, wl + O_ENCW + i * 65536, DD,
            nullptr, yh, yl, DD, DD, 0, 0, 0, 1.f,
            enc_asrc + i * 256, enc_adst + i * 256, ssrc, sdst);
        gat_agg<4><<<NN, blk>>>(yh, yl, ssrc, sdst, idxb, enc_b + i * DD, xh, xl, nullptr, 1);
        xih = xh; xil = xl;
    }

    // ---- transformer bottleneck: 2 layers (split-KV flash attention)
    for (int i = 0; i < 2; i++) {
        gemm_bf3<128, 4><<<dim3(6, 32), blk>>>(xh, xl, DD,
            wh + O_WQKV + i * 196608, wl + O_WQKV + i * 196608, DD,
            tr_bqkv + i * 768, qkvh, qkvl, 768, DD, 0, 0, 0, 1.f,
            nullptr, nullptr, nullptr, nullptr);
        flash_attn<<<dim3(32, 4, 2), blk>>>(qkvh, qkvl, opb, mvb, lvb);
        attn_merge<<<NN, blk>>>(opb, mvb, lvb, yh, yl);
        gemm_bf3<64, 0><<<dim3(4, 32), blk>>>(yh, yl, DD,
            wh + O_WO + i * 65536, wl + O_WO + i * 65536, DD,
            tr_bo + i * DD, th, tl, DD, DD, 0, 0, 0, 1.f,
            nullptr, nullptr, nullptr, nullptr);
        add_ln_kernel<<<NN, blk>>>(xh, xl, th, tl, ln1g + i * DD, ln1b + i * DD, xh, xl);
        gemm_bf3<128, 1><<<dim3(4, 32), blk>>>(xh, xl, DD,
            wh + O_W1 + i * 131072, wl + O_W1 + i * 131072, DD,
            tr_b1 + i * 512, ffh, ffl, 512, DD, 0, 0, 0, 1.f,
            nullptr, nullptr, nullptr, nullptr);
        gemm_bf3<64, 0><<<dim3(4, 32), blk>>>(ffh, ffl, 512,
            wh + O_W2 + i * 131072, wl + O_W2 + i * 131072, 512,
            tr_b2 + i * DD, th, tl, DD, 512, 0, 0, 0, 1.f,
            nullptr, nullptr, nullptr, nullptr);
        add_ln_kernel<<<NN, blk>>>(xh, xl, th, tl, ln2g + i * DD, ln2b + i * DD, xh, xl);
    }

    // ---- skip connection fused into GEMM (ACT=3: C += window @ skip_w + b)
    gemm_bf3<64, 3><<<dim3(4, 32), blk>>>(winh, winl, DD, wh + O_SKIP, wl + O_SKIP, DD,
        skip_b, xh, xl, DD, DD, 0, 0, 0, 1.f,
        nullptr, nullptr, nullptr, nullptr);

    // ---- decoder: 2x GAT(4 heads)+relu (scores fused), then single-head GAT
    for (int i = 0; i < 2; i++) {
        gemm_bf3<64, 5><<<dim3(4, 32), blk>>>(xh, xl, DD,
            wh + O_DECW + i * 65536, wl + O_DECW + i * 65536, DD,
            nullptr, yh, yl, DD, DD, 0, 0, 0, 1.f,
            dec_asrc + i * 256, dec_adst + i * 256, ssrc, sdst);
        gat_agg<4><<<NN, blk>>>(yh, yl, ssrc, sdst, idxb, dec_b + i * DD, xh, xl, nullptr, 1);
    }
    gemm_bf3<64, 0><<<dim3(4, 32), blk>>>(xh, xl, DD, wh + O_DECL, wl + O_DECL, DD,
        nullptr, yh, yl, DD, DD, 0, 0, 0, 1.f,
        nullptr, nullptr, nullptr, nullptr);
    gat_scores<<<NN, blk>>>(yh, yl, dec_lasrc, dec_ladst, ssrc, sdst, 1);
    gat_agg<1><<<NN, blk>>>(yh, yl, ssrc, sdst, idxb, dec_lb, nullptr, nullptr, tb, 0);

    // ---- output: transpose to [256, 4096]
    transpose_kernel<<<dim3(8, 128), dim3(32, 8)>>>(tb, (float*)d_out);
}